// round 2
// baseline (speedup 1.0000x reference)
#include <cuda_runtime.h>
#include <math.h>
#include <stdint.h>

// Problem constants
#define BB 8
#define SS 500
#define DD 1024
#define HH 16
#define LL 4
#define FF 4096
#define VV 30000
#define DK 64
#define MM (BB*SS)          // 4000 rows
#define LN_EPS 1e-6f

// ----------------------------------------------------------------------------
// Scratch (device globals: allocation-free)
// ----------------------------------------------------------------------------
__device__ float g_h[(size_t)MM*DD];
__device__ float g_y[(size_t)MM*DD];
__device__ float g_q[(size_t)MM*DD];
__device__ float g_k[(size_t)MM*DD];
__device__ float g_v[(size_t)MM*DD];
__device__ float g_o[(size_t)MM*DD];
__device__ float g_f[(size_t)MM*FF];
__device__ float g_s[(size_t)BB*HH*SS*SS];   // attention scores/probs (128 MB)

// ----------------------------------------------------------------------------
// Block reductions (256 threads)
// ----------------------------------------------------------------------------
__device__ __forceinline__ float blk_sum256(float v) {
    __shared__ float sh[8];
    #pragma unroll
    for (int o = 16; o > 0; o >>= 1) v += __shfl_down_sync(0xffffffffu, v, o);
    __syncthreads();                       // protect sh reuse across calls
    if ((threadIdx.x & 31) == 0) sh[threadIdx.x >> 5] = v;
    __syncthreads();
    float t = 0.f;
    #pragma unroll
    for (int i = 0; i < 8; i++) t += sh[i];
    return t;
}

__device__ __forceinline__ float blk_max256(float v) {
    __shared__ float sh[8];
    #pragma unroll
    for (int o = 16; o > 0; o >>= 1) v = fmaxf(v, __shfl_down_sync(0xffffffffu, v, o));
    __syncthreads();
    if ((threadIdx.x & 31) == 0) sh[threadIdx.x >> 5] = v;
    __syncthreads();
    float t = -INFINITY;
    #pragma unroll
    for (int i = 0; i < 8; i++) t = fmaxf(t, sh[i]);
    return t;
}

// ----------------------------------------------------------------------------
// Embedding + sinusoidal positional encoding
// ----------------------------------------------------------------------------
__global__ void embed_k(const int* __restrict__ x, const float* __restrict__ emb,
                        float* __restrict__ h) {
    int idx = blockIdx.x * blockDim.x + threadIdx.x;
    if (idx >= MM * DD) return;
    int row = idx >> 10;            // DD = 1024
    int d   = idx & 1023;
    int s   = row % SS;
    int tok = x[row];
    int i2  = d & ~1;               // 2*(d/2)
    float div = expf(-(float)i2 * (logf(10000.0f) / (float)DD));
    float ang = (float)s * div;
    float pe  = (d & 1) ? cosf(ang) : sinf(ang);
    h[idx] = emb[(size_t)tok * DD + d] + pe;
}

// ----------------------------------------------------------------------------
// LayerNorm: torch semantics — var with ddof=1, eps added to std
// one block (256 threads) per row of 1024
// ----------------------------------------------------------------------------
__global__ __launch_bounds__(256) void layernorm_k(
    const float* __restrict__ x, const float* __restrict__ a,
    const float* __restrict__ b, float* __restrict__ out) {
    int row = blockIdx.x;
    const float* xp = x + (size_t)row * DD;
    int t4 = threadIdx.x * 4;
    float4 xv = *(const float4*)(xp + t4);
    float s = xv.x + xv.y + xv.z + xv.w;
    float mean = blk_sum256(s) * (1.0f / DD);
    float d0 = xv.x - mean, d1 = xv.y - mean, d2 = xv.z - mean, d3 = xv.w - mean;
    float sq = d0*d0 + d1*d1 + d2*d2 + d3*d3;
    float var = blk_sum256(sq) * (1.0f / (DD - 1));
    float inv = 1.0f / (sqrtf(var) + LN_EPS);
    float4 av = *(const float4*)(a + t4);
    float4 bv = *(const float4*)(b + t4);
    float4 r;
    r.x = av.x * d0 * inv + bv.x;
    r.y = av.y * d1 * inv + bv.y;
    r.z = av.z * d2 * inv + bv.z;
    r.w = av.w * d3 * inv + bv.w;
    *(float4*)(out + (size_t)row * DD + t4) = r;
}

// ----------------------------------------------------------------------------
// SGEMM: C[M,N] = A[M,K] @ B[K,N] + bias[N] (+res) (+relu)
// 128x128 block tile, BK=8, 8x8 per thread, 256 threads
// Requires: N % 128 == 0, K % 8 == 0. M guarded.
// ----------------------------------------------------------------------------
template<bool RELU, bool RES>
__global__ __launch_bounds__(256) void sgemm_k(
    const float* __restrict__ A, const float* __restrict__ Bm,
    const float* __restrict__ bias, const float* __restrict__ res,
    float* __restrict__ C, int M, int N, int K) {
    __shared__ float As[8][128];
    __shared__ float Bs[8][128];
    const int tid  = threadIdx.x;
    const int bm   = blockIdx.y * 128;
    const int bn   = blockIdx.x * 128;
    const int tx   = tid & 15;
    const int ty   = tid >> 4;
    const int arow = tid >> 1;
    const int acol = (tid & 1) * 4;
    const int brow = tid >> 5;
    const int bcol = (tid & 31) * 4;

    float acc[8][8];
    #pragma unroll
    for (int i = 0; i < 8; i++)
        #pragma unroll
        for (int j = 0; j < 8; j++) acc[i][j] = 0.f;

    const bool aok = (bm + arow) < M;
    const float* Aptr = A + (size_t)(bm + arow) * K + acol;
    const float* Bptr = Bm + (size_t)brow * N + bn + bcol;

    for (int k0 = 0; k0 < K; k0 += 8) {
        float4 av = make_float4(0.f, 0.f, 0.f, 0.f);
        if (aok) av = *(const float4*)(Aptr + k0);
        As[acol + 0][arow] = av.x;
        As[acol + 1][arow] = av.y;
        As[acol + 2][arow] = av.z;
        As[acol + 3][arow] = av.w;
        *(float4*)&Bs[brow][bcol] = *(const float4*)(Bptr + (size_t)k0 * N);
        __syncthreads();
        #pragma unroll
        for (int k = 0; k < 8; k++) {
            float ar[8], br[8];
            *(float4*)&ar[0] = *(const float4*)&As[k][ty * 8];
            *(float4*)&ar[4] = *(const float4*)&As[k][ty * 8 + 4];
            *(float4*)&br[0] = *(const float4*)&Bs[k][tx * 8];
            *(float4*)&br[4] = *(const float4*)&Bs[k][tx * 8 + 4];
            #pragma unroll
            for (int i = 0; i < 8; i++)
                #pragma unroll
                for (int j = 0; j < 8; j++)
                    acc[i][j] = fmaf(ar[i], br[j], acc[i][j]);
        }
        __syncthreads();
    }

    #pragma unroll
    for (int i = 0; i < 8; i++) {
        int gm = bm + ty * 8 + i;
        if (gm >= M) continue;
        float* Cp = C + (size_t)gm * N + bn + tx * 8;
        #pragma unroll
        for (int j = 0; j < 8; j += 4) {
            float4 v;
            v.x = acc[i][j]; v.y = acc[i][j+1]; v.z = acc[i][j+2]; v.w = acc[i][j+3];
            float4 bb = *(const float4*)(bias + bn + tx * 8 + j);
            v.x += bb.x; v.y += bb.y; v.z += bb.z; v.w += bb.w;
            if (RES) {
                float4 r = *(const float4*)(res + (size_t)gm * N + bn + tx * 8 + j);
                v.x += r.x; v.y += r.y; v.z += r.z; v.w += r.w;
            }
            if (RELU) {
                v.x = fmaxf(v.x, 0.f); v.y = fmaxf(v.y, 0.f);
                v.z = fmaxf(v.z, 0.f); v.w = fmaxf(v.w, 0.f);
            }
            *(float4*)(Cp + j) = v;
        }
    }
}

// ----------------------------------------------------------------------------
// Attention scores: S[bh, q, k] = (Q[b,q,h,:] . K[b,k,h,:]) / sqrt(DK)
// Q,K stored as [B,S,D] with head h at column offset h*64.
// 64x64 output tile / block, 256 threads (4x4 per thread), K-chunks of 16.
// ----------------------------------------------------------------------------
__global__ __launch_bounds__(256) void attn_scores_k(
    const float* __restrict__ Q, const float* __restrict__ Km,
    float* __restrict__ Sc) {
    int bh = blockIdx.z;
    int b = bh / HH, h = bh % HH;
    int q0 = blockIdx.y * 64;
    int k0 = blockIdx.x * 64;
    __shared__ float Qs[16][64];
    __shared__ float Ks[16][64];
    int tid = threadIdx.x;
    int tx = tid & 15, ty = tid >> 4;
    int lr = tid >> 2, lc = (tid & 3) * 4;
    const float* Qbase = Q + (size_t)b * SS * DD + h * 64;
    const float* Kbase = Km + (size_t)b * SS * DD + h * 64;
    float acc[4][4];
    #pragma unroll
    for (int i = 0; i < 4; i++)
        #pragma unroll
        for (int j = 0; j < 4; j++) acc[i][j] = 0.f;

    for (int kc = 0; kc < DK; kc += 16) {
        float4 qv = make_float4(0.f,0.f,0.f,0.f);
        if (q0 + lr < SS) qv = *(const float4*)(Qbase + (size_t)(q0 + lr) * DD + kc + lc);
        Qs[lc+0][lr] = qv.x; Qs[lc+1][lr] = qv.y; Qs[lc+2][lr] = qv.z; Qs[lc+3][lr] = qv.w;
        float4 kv = make_float4(0.f,0.f,0.f,0.f);
        if (k0 + lr < SS) kv = *(const float4*)(Kbase + (size_t)(k0 + lr) * DD + kc + lc);
        Ks[lc+0][lr] = kv.x; Ks[lc+1][lr] = kv.y; Ks[lc+2][lr] = kv.z; Ks[lc+3][lr] = kv.w;
        __syncthreads();
        #pragma unroll
        for (int k = 0; k < 16; k++) {
            float qr[4], kr[4];
            *(float4*)qr = *(const float4*)&Qs[k][ty * 4];
            *(float4*)kr = *(const float4*)&Ks[k][tx * 4];
            #pragma unroll
            for (int i = 0; i < 4; i++)
                #pragma unroll
                for (int j = 0; j < 4; j++)
                    acc[i][j] = fmaf(qr[i], kr[j], acc[i][j]);
        }
        __syncthreads();
    }
    float* Sp = Sc + (size_t)bh * SS * SS;
    #pragma unroll
    for (int i = 0; i < 4; i++) {
        int qq = q0 + ty * 4 + i;
        if (qq >= SS) continue;
        #pragma unroll
        for (int j = 0; j < 4; j++) {
            int kk = k0 + tx * 4 + j;
            if (kk < SS) Sp[(size_t)qq * SS + kk] = acc[i][j] * 0.125f;
        }
    }
}

// ----------------------------------------------------------------------------
// Softmax over last dim (length SS) — one block per (bh, q) row
// ----------------------------------------------------------------------------
__global__ __launch_bounds__(256) void softmax_k(float* __restrict__ Sc) {
    float* p = Sc + (size_t)blockIdx.x * SS;
    int tid = threadIdx.x;
    float m = -INFINITY;
    for (int i = tid; i < SS; i += 256) m = fmaxf(m, p[i]);
    m = blk_max256(m);
    float sum = 0.f;
    for (int i = tid; i < SS; i += 256) {
        float e = expf(p[i] - m);
        p[i] = e;
        sum += e;
    }
    sum = blk_sum256(sum);
    float inv = 1.0f / sum;
    for (int i = tid; i < SS; i += 256) p[i] *= inv;
}

// ----------------------------------------------------------------------------
// P @ V : O[b,q,h,:] = sum_k P[bh,q,k] * V[b,k,h,:]
// 64 q-rows x 64 cols per block; K-chunks of 16.
// ----------------------------------------------------------------------------
__global__ __launch_bounds__(256) void attn_pv_k(
    const float* __restrict__ V, const float* __restrict__ P,
    float* __restrict__ O) {
    int bh = blockIdx.y;
    int b = bh / HH, h = bh % HH;
    int q0 = blockIdx.x * 64;
    __shared__ float Ps[64][17];
    __shared__ float Vs[16][64];
    int tid = threadIdx.x;
    int tx = tid & 15, ty = tid >> 4;
    int pr = tid >> 2, pc0 = (tid & 3) * 4;
    int vr = tid >> 4, vc = (tid & 15) * 4;
    const float* Pp = P + (size_t)bh * SS * SS;
    const float* Vp = V + (size_t)b * SS * DD + h * 64;
    float acc[4][4];
    #pragma unroll
    for (int i = 0; i < 4; i++)
        #pragma unroll
        for (int j = 0; j < 4; j++) acc[i][j] = 0.f;

    for (int k0 = 0; k0 < SS; k0 += 16) {
        int qq = q0 + pr;
        #pragma unroll
        for (int c = 0; c < 4; c++) {
            int kk = k0 + pc0 + c;
            Ps[pr][pc0 + c] = (qq < SS && kk < SS) ? Pp[(size_t)qq * SS + kk] : 0.f;
        }
        float4 vv = make_float4(0.f,0.f,0.f,0.f);
        if (k0 + vr < SS) vv = *(const float4*)(Vp + (size_t)(k0 + vr) * DD + vc);
        *(float4*)&Vs[vr][vc] = vv;
        __syncthreads();
        #pragma unroll
        for (int k = 0; k < 16; k++) {
            float pv[4];
            #pragma unroll
            for (int i = 0; i < 4; i++) pv[i] = Ps[ty * 4 + i][k];
            float4 vvv = *(const float4*)&Vs[k][tx * 4];
            float vr4[4] = {vvv.x, vvv.y, vvv.z, vvv.w};
            #pragma unroll
            for (int i = 0; i < 4; i++)
                #pragma unroll
                for (int j = 0; j < 4; j++)
                    acc[i][j] = fmaf(pv[i], vr4[j], acc[i][j]);
        }
        __syncthreads();
    }
    #pragma unroll
    for (int i = 0; i < 4; i++) {
        int qq = q0 + ty * 4 + i;
        if (qq >= SS) continue;
        float4 v = make_float4(acc[i][0], acc[i][1], acc[i][2], acc[i][3]);
        *(float4*)(O + (size_t)(b * SS + qq) * DD + h * 64 + tx * 4) = v;
    }
}

// ----------------------------------------------------------------------------
// Host: orchestrate the whole encoder (graph-capturable: launches only)
// ----------------------------------------------------------------------------
extern "C" void kernel_launch(void* const* d_in, const int* in_sizes, int n_in,
                              void* d_out, int out_size) {
    const int*   x      = (const int*)d_in[0];
    const float* emb    = (const float*)d_in[1];
    const float* attn_w = (const float*)d_in[2];
    const float* attn_b = (const float*)d_in[3];
    const float* ln_a   = (const float*)d_in[4];
    const float* ln_b   = (const float*)d_in[5];
    const float* w1     = (const float*)d_in[6];
    const float* b1     = (const float*)d_in[7];
    const float* w2     = (const float*)d_in[8];
    const float* b2     = (const float*)d_in[9];
    const float* na     = (const float*)d_in[10];
    const float* nb     = (const float*)d_in[11];
    float* out = (float*)d_out;

    float *h, *y, *q, *k, *v, *o, *f, *s;
    cudaGetSymbolAddress((void**)&h, g_h);
    cudaGetSymbolAddress((void**)&y, g_y);
    cudaGetSymbolAddress((void**)&q, g_q);
    cudaGetSymbolAddress((void**)&k, g_k);
    cudaGetSymbolAddress((void**)&v, g_v);
    cudaGetSymbolAddress((void**)&o, g_o);
    cudaGetSymbolAddress((void**)&f, g_f);
    cudaGetSymbolAddress((void**)&s, g_s);

    embed_k<<<(MM * DD + 255) / 256, 256>>>(x, emb, h);

    dim3 gD(DD / 128, (MM + 127) / 128);   // (8, 32)
    dim3 gF(FF / 128, (MM + 127) / 128);   // (32, 32)
    dim3 gS(8, 8, BB * HH);                // score tiles
    dim3 gPV(8, BB * HH);

    for (int l = 0; l < LL; l++) {
        const float* W  = attn_w + (size_t)l * 4 * DD * DD;
        const float* Wb = attn_b + (size_t)l * 4 * DD;
        const float* la = ln_a + (size_t)l * 2 * DD;
        const float* lb = ln_b + (size_t)l * 2 * DD;

        // --- attention sublayer ---
        layernorm_k<<<MM, 256>>>(h, la, lb, y);
        sgemm_k<false, false><<<gD, 256>>>(y, W,                Wb,          nullptr, q, MM, DD, DD);
        sgemm_k<false, false><<<gD, 256>>>(y, W + (size_t)DD*DD,   Wb + DD,  nullptr, k, MM, DD, DD);
        sgemm_k<false, false><<<gD, 256>>>(y, W + (size_t)2*DD*DD, Wb + 2*DD, nullptr, v, MM, DD, DD);
        attn_scores_k<<<gS, 256>>>(q, k, s);
        softmax_k<<<BB * HH * SS, 256>>>(s);
        attn_pv_k<<<gPV, 256>>>(v, s, o);
        sgemm_k<false, true><<<gD, 256>>>(o, W + (size_t)3*DD*DD, Wb + 3*DD, h, h, MM, DD, DD);

        // --- feed-forward sublayer ---
        layernorm_k<<<MM, 256>>>(h, la + DD, lb + DD, y);
        sgemm_k<true,  false><<<gF, 256>>>(y, w1 + (size_t)l*DD*FF, b1 + (size_t)l*FF, nullptr, f, MM, FF, DD);
        sgemm_k<false, true ><<<gD, 256>>>(f, w2 + (size_t)l*FF*DD, b2 + (size_t)l*DD, h, h, MM, DD, FF);
    }

    layernorm_k<<<MM, 256>>>(h, na, nb, out);
}

// round 3
// speedup vs baseline: 1.8815x; 1.8815x over previous
#include <cuda_runtime.h>
#include <cuda_bf16.h>
#include <math.h>
#include <stdint.h>

#define BB 8
#define SS 500
#define DD 1024
#define HH 16
#define LL 4
#define FF 4096
#define MM (BB*SS)          // 4000
#define QKVN (3*DD)         // 3072
#define LN_EPS 1e-6f

typedef __nv_bfloat16 bf16;

// ----------------------------------------------------------------------------
// Scratch (device globals; allocation-free)
// ----------------------------------------------------------------------------
__device__ __align__(128) float g_h[(size_t)MM*DD];
__device__ __align__(128) float g_qkv[(size_t)MM*QKVN];
__device__ __align__(128) float g_s[(size_t)BB*HH*SS*SS];
__device__ __align__(128) bf16 g_yh[(size_t)MM*DD], g_yl[(size_t)MM*DD];
__device__ __align__(128) bf16 g_oh[(size_t)MM*DD], g_ol[(size_t)MM*DD];
__device__ __align__(128) bf16 g_fh[(size_t)MM*FF], g_fl[(size_t)MM*FF];
// transposed weights, hi/lo bf16, layout [N][K]
__device__ __align__(128) bf16 g_wqkvh[(size_t)LL*QKVN*DD], g_wqkvl[(size_t)LL*QKVN*DD];
__device__ __align__(128) bf16 g_woh[(size_t)LL*DD*DD],     g_wol[(size_t)LL*DD*DD];
__device__ __align__(128) bf16 g_w1h[(size_t)LL*FF*DD],     g_w1l[(size_t)LL*FF*DD];
__device__ __align__(128) bf16 g_w2h[(size_t)LL*DD*FF],     g_w2l[(size_t)LL*DD*FF];

// ----------------------------------------------------------------------------
// Helpers
// ----------------------------------------------------------------------------
__device__ __forceinline__ float blk_sum256(float v) {
    __shared__ float sh[8];
    #pragma unroll
    for (int o = 16; o > 0; o >>= 1) v += __shfl_down_sync(0xffffffffu, v, o);
    __syncthreads();
    if ((threadIdx.x & 31) == 0) sh[threadIdx.x >> 5] = v;
    __syncthreads();
    float t = 0.f;
    #pragma unroll
    for (int i = 0; i < 8; i++) t += sh[i];
    return t;
}
__device__ __forceinline__ float blk_max256(float v) {
    __shared__ float sh[8];
    #pragma unroll
    for (int o = 16; o > 0; o >>= 1) v = fmaxf(v, __shfl_down_sync(0xffffffffu, v, o));
    __syncthreads();
    if ((threadIdx.x & 31) == 0) sh[threadIdx.x >> 5] = v;
    __syncthreads();
    float t = -INFINITY;
    #pragma unroll
    for (int i = 0; i < 8; i++) t = fmaxf(t, sh[i]);
    return t;
}

__device__ __forceinline__ void cp16(uint32_t dst, const void* src, int sz) {
    asm volatile("cp.async.cg.shared.global [%0], [%1], 16, %2;\n"
                 :: "r"(dst), "l"(src), "r"(sz));
}
__device__ __forceinline__ void cp_commit() { asm volatile("cp.async.commit_group;\n"); }
template<int N> __device__ __forceinline__ void cp_wait() {
    asm volatile("cp.async.wait_group %0;\n" :: "n"(N));
}
__device__ __forceinline__ void mma16816(float* c, const uint32_t* a, const uint32_t* b) {
    asm volatile("mma.sync.aligned.m16n8k16.row.col.f32.bf16.bf16.f32 "
        "{%0,%1,%2,%3},{%4,%5,%6,%7},{%8,%9},{%0,%1,%2,%3};\n"
        : "+f"(c[0]), "+f"(c[1]), "+f"(c[2]), "+f"(c[3])
        : "r"(a[0]), "r"(a[1]), "r"(a[2]), "r"(a[3]), "r"(b[0]), "r"(b[1]));
}
__device__ __forceinline__ void split_pair(float v0, float v1, uint32_t& hw, uint32_t& lw) {
    bf16 h0 = __float2bfloat16(v0), h1 = __float2bfloat16(v1);
    bf16 l0 = __float2bfloat16(v0 - __bfloat162float(h0));
    bf16 l1 = __float2bfloat16(v1 - __bfloat162float(h1));
    __nv_bfloat162 hh; hh.x = h0; hh.y = h1;
    __nv_bfloat162 ll; ll.x = l0; ll.y = l1;
    hw = *(uint32_t*)&hh; lw = *(uint32_t*)&ll;
}

// ----------------------------------------------------------------------------
// Embedding + positional encoding
// ----------------------------------------------------------------------------
__global__ void embed_k(const int* __restrict__ x, const float* __restrict__ emb,
                        float* __restrict__ h) {
    int idx = blockIdx.x * blockDim.x + threadIdx.x;
    if (idx >= MM * DD) return;
    int row = idx >> 10, d = idx & 1023;
    int s = row % SS;
    int tok = x[row];
    int i2 = d & ~1;
    float div = expf(-(float)i2 * (logf(10000.0f) / (float)DD));
    float ang = (float)s * div;
    float pe = (d & 1) ? cosf(ang) : sinf(ang);
    h[idx] = emb[(size_t)tok * DD + d] + pe;
}

// ----------------------------------------------------------------------------
// LayerNorm (torch: ddof=1, eps on std). fp32-out and split(hi/lo bf16) variants
// ----------------------------------------------------------------------------
__global__ __launch_bounds__(256) void layernorm_k(
    const float* __restrict__ x, const float* __restrict__ a,
    const float* __restrict__ b, float* __restrict__ out) {
    int row = blockIdx.x;
    const float* xp = x + (size_t)row * DD;
    int t4 = threadIdx.x * 4;
    float4 xv = *(const float4*)(xp + t4);
    float mean = blk_sum256(xv.x + xv.y + xv.z + xv.w) * (1.0f / DD);
    float d0 = xv.x - mean, d1 = xv.y - mean, d2 = xv.z - mean, d3 = xv.w - mean;
    float var = blk_sum256(d0*d0 + d1*d1 + d2*d2 + d3*d3) * (1.0f / (DD - 1));
    float inv = 1.0f / (sqrtf(var) + LN_EPS);
    float4 av = *(const float4*)(a + t4);
    float4 bv = *(const float4*)(b + t4);
    float4 r;
    r.x = av.x * d0 * inv + bv.x; r.y = av.y * d1 * inv + bv.y;
    r.z = av.z * d2 * inv + bv.z; r.w = av.w * d3 * inv + bv.w;
    *(float4*)(out + (size_t)row * DD + t4) = r;
}

__global__ __launch_bounds__(256) void ln_split_k(
    const float* __restrict__ x, const float* __restrict__ a,
    const float* __restrict__ b, bf16* __restrict__ yh, bf16* __restrict__ yl) {
    int row = blockIdx.x;
    const float* xp = x + (size_t)row * DD;
    int t4 = threadIdx.x * 4;
    float4 xv = *(const float4*)(xp + t4);
    float mean = blk_sum256(xv.x + xv.y + xv.z + xv.w) * (1.0f / DD);
    float d0 = xv.x - mean, d1 = xv.y - mean, d2 = xv.z - mean, d3 = xv.w - mean;
    float var = blk_sum256(d0*d0 + d1*d1 + d2*d2 + d3*d3) * (1.0f / (DD - 1));
    float inv = 1.0f / (sqrtf(var) + LN_EPS);
    float4 av = *(const float4*)(a + t4);
    float4 bv = *(const float4*)(b + t4);
    float v0 = av.x * d0 * inv + bv.x, v1 = av.y * d1 * inv + bv.y;
    float v2 = av.z * d2 * inv + bv.z, v3 = av.w * d3 * inv + bv.w;
    uint32_t h01, l01, h23, l23;
    split_pair(v0, v1, h01, l01);
    split_pair(v2, v3, h23, l23);
    uint32_t* ph = (uint32_t*)(yh + (size_t)row * DD + t4);
    uint32_t* pl = (uint32_t*)(yl + (size_t)row * DD + t4);
    ph[0] = h01; ph[1] = h23; pl[0] = l01; pl[1] = l23;
}

// ----------------------------------------------------------------------------
// Weight transpose + hi/lo bf16 conversion: W[K][N] -> T[N][K]
// ----------------------------------------------------------------------------
__global__ void convt_k(const float* __restrict__ W, bf16* __restrict__ Th,
                        bf16* __restrict__ Tl, int K, int N) {
    __shared__ float t[32][33];
    int n0 = blockIdx.x * 32, k0 = blockIdx.y * 32;
    int tx = threadIdx.x, ty = threadIdx.y;
    #pragma unroll
    for (int i = ty; i < 32; i += 8) t[i][tx] = W[(size_t)(k0 + i) * N + n0 + tx];
    __syncthreads();
    #pragma unroll
    for (int i = ty; i < 32; i += 8) {
        float v = t[tx][i];
        bf16 h = __float2bfloat16(v);
        Th[(size_t)(n0 + i) * K + k0 + tx] = h;
        Tl[(size_t)(n0 + i) * K + k0 + tx] = __float2bfloat16(v - __bfloat162float(h));
    }
}

// ----------------------------------------------------------------------------
// bf16x3 tensor-core GEMM:  C[M,N] = A[M,K] @ B^T[N,K]  (+bias)(+res)(+relu/split)
// MODE 0: Cf = acc + bias          (fp32 out)
// MODE 1: Cf = acc + bias + Cf     (fp32, in-place residual)
// MODE 2: relu(acc + bias) -> split hi/lo bf16 (Oh, Ol)
// 128x128 tile, BK=32, 256 threads, 8 warps (2x4 of 64x32), cp.async x2 stages
// ----------------------------------------------------------------------------
#define SW 20            // padded word stride per 32-elem (16-word) row
#define STAGE_W 10240    // words per stage (4 arrays * 128 * SW)
#define AH_OFF 0
#define AL_OFF 2560
#define BH_OFF 5120
#define BL_OFF 7680
#define GEMM_SMEM (2 * STAGE_W * 4)

template<int MODE>
__global__ __launch_bounds__(256) void gemm_k(
    const bf16* __restrict__ Ah, const bf16* __restrict__ Al,
    const bf16* __restrict__ Bh, const bf16* __restrict__ Bl,
    const float* __restrict__ bias, float* __restrict__ Cf,
    bf16* __restrict__ Oh, bf16* __restrict__ Ol,
    int M, int N, int K) {
    extern __shared__ uint32_t sm[];
    uint32_t sbase = (uint32_t)__cvta_generic_to_shared(sm);
    const int tid = threadIdx.x;
    const int bm = blockIdx.y * 128;
    const int bn = blockIdx.x * 128;
    const int lane = tid & 31, warp = tid >> 5;
    const int wm = warp >> 2, wn = warp & 3;     // warp tile: 64x32
    const int g = lane >> 2, tig = lane & 3;

    float acc[4][4][4];
    #pragma unroll
    for (int i = 0; i < 4; i++)
        #pragma unroll
        for (int j = 0; j < 4; j++)
            #pragma unroll
            for (int r = 0; r < 4; r++) acc[i][j][r] = 0.f;

    const int nK = K >> 5;

    // prefetch helper (inlined twice)
    #define PREFETCH(stg, k0)                                                        \
    {                                                                                \
        uint32_t sb = sbase + (stg) * (STAGE_W * 4);                                 \
        _Pragma("unroll")                                                            \
        for (int i = 0; i < 2; i++) {                                                \
            int idx = tid + 256 * i;                                                 \
            int row = idx >> 2, cw = idx & 3;                                        \
            int gr = bm + row;                                                       \
            int sz = (gr < M) ? 16 : 0;                                              \
            int grc = (gr < M) ? gr : 0;                                             \
            const bf16* pa  = Ah + (size_t)grc * K + (k0) + cw * 8;                  \
            const bf16* pal = Al + (size_t)grc * K + (k0) + cw * 8;                  \
            cp16(sb + (AH_OFF + row * SW + cw * 4) * 4, pa, sz);                     \
            cp16(sb + (AL_OFF + row * SW + cw * 4) * 4, pal, sz);                    \
            int gn = bn + row;                                                       \
            const bf16* pb  = Bh + (size_t)gn * K + (k0) + cw * 8;                   \
            const bf16* pbl = Bl + (size_t)gn * K + (k0) + cw * 8;                   \
            cp16(sb + (BH_OFF + row * SW + cw * 4) * 4, pb, 16);                     \
            cp16(sb + (BL_OFF + row * SW + cw * 4) * 4, pbl, 16);                    \
        }                                                                            \
    }

    PREFETCH(0, 0);
    cp_commit();

    int stage = 0;
    for (int it = 0; it < nK; it++) {
        if (it + 1 < nK) {
            PREFETCH(stage ^ 1, (it + 1) * 32);
            cp_commit();
            cp_wait<1>();
        } else {
            cp_wait<0>();
        }
        __syncthreads();

        const uint32_t* sAh = sm + stage * STAGE_W + AH_OFF;
        const uint32_t* sAl = sm + stage * STAGE_W + AL_OFF;
        const uint32_t* sBh = sm + stage * STAGE_W + BH_OFF;
        const uint32_t* sBl = sm + stage * STAGE_W + BL_OFF;

        #pragma unroll
        for (int ks = 0; ks < 2; ks++) {
            const int kw = ks * 8;
            uint32_t fah[4][4], fal[4][4], fbh[4][2], fbl[4][2];
            #pragma unroll
            for (int i = 0; i < 4; i++) {
                int r0 = (wm * 64 + i * 16 + g) * SW;
                fah[i][0] = sAh[r0 + kw + tig];
                fah[i][1] = sAh[r0 + 8 * SW + kw + tig];
                fah[i][2] = sAh[r0 + kw + tig + 4];
                fah[i][3] = sAh[r0 + 8 * SW + kw + tig + 4];
                fal[i][0] = sAl[r0 + kw + tig];
                fal[i][1] = sAl[r0 + 8 * SW + kw + tig];
                fal[i][2] = sAl[r0 + kw + tig + 4];
                fal[i][3] = sAl[r0 + 8 * SW + kw + tig + 4];
            }
            #pragma unroll
            for (int j = 0; j < 4; j++) {
                int rn = (wn * 32 + j * 8 + g) * SW;
                fbh[j][0] = sBh[rn + kw + tig];
                fbh[j][1] = sBh[rn + kw + tig + 4];
                fbl[j][0] = sBl[rn + kw + tig];
                fbl[j][1] = sBl[rn + kw + tig + 4];
            }
            #pragma unroll
            for (int i = 0; i < 4; i++)
                #pragma unroll
                for (int j = 0; j < 4; j++) {
                    mma16816(acc[i][j], fah[i], fbh[j]);
                    mma16816(acc[i][j], fah[i], fbl[j]);
                    mma16816(acc[i][j], fal[i], fbh[j]);
                }
        }
        __syncthreads();
        stage ^= 1;
    }

    // epilogue
    #pragma unroll
    for (int i = 0; i < 4; i++) {
        #pragma unroll
        for (int j = 0; j < 4; j++) {
            int r0 = bm + wm * 64 + i * 16 + g;
            int c = bn + wn * 32 + j * 8 + tig * 2;
            float bx = bias[c], by = bias[c + 1];
            #pragma unroll
            for (int half = 0; half < 2; half++) {
                int r = r0 + half * 8;
                if (r >= M) continue;
                float v0 = acc[i][j][half * 2 + 0] + bx;
                float v1 = acc[i][j][half * 2 + 1] + by;
                if (MODE == 1) {
                    float2 old = *(float2*)(Cf + (size_t)r * N + c);
                    v0 += old.x; v1 += old.y;
                }
                if (MODE == 2) {
                    v0 = fmaxf(v0, 0.f); v1 = fmaxf(v1, 0.f);
                    uint32_t hw, lw;
                    split_pair(v0, v1, hw, lw);
                    *(uint32_t*)(Oh + (size_t)r * N + c) = hw;
                    *(uint32_t*)(Ol + (size_t)r * N + c) = lw;
                } else {
                    float2 o; o.x = v0; o.y = v1;
                    *(float2*)(Cf + (size_t)r * N + c) = o;
                }
            }
        }
    }
}

// ----------------------------------------------------------------------------
// Attention (fp32): scores, softmax, PV (PV writes hi/lo bf16)
// q at col 0, k at 1024, v at 2048 within qkv[M][3072]
// ----------------------------------------------------------------------------
__global__ __launch_bounds__(256) void attn_scores_k(
    const float* __restrict__ QKV, float* __restrict__ Sc) {
    int bh = blockIdx.z;
    int b = bh / HH, h = bh % HH;
    int q0 = blockIdx.y * 64, k0 = blockIdx.x * 64;
    __shared__ float Qs[16][64];
    __shared__ float Ks[16][64];
    int tid = threadIdx.x;
    int tx = tid & 15, ty = tid >> 4;
    int lr = tid >> 2, lc = (tid & 3) * 4;
    const float* Qbase = QKV + (size_t)b * SS * QKVN + h * 64;
    const float* Kbase = QKV + (size_t)b * SS * QKVN + DD + h * 64;
    float acc[4][4];
    #pragma unroll
    for (int i = 0; i < 4; i++)
        #pragma unroll
        for (int j = 0; j < 4; j++) acc[i][j] = 0.f;

    for (int kc = 0; kc < 64; kc += 16) {
        float4 qv = make_float4(0.f, 0.f, 0.f, 0.f);
        if (q0 + lr < SS) qv = *(const float4*)(Qbase + (size_t)(q0 + lr) * QKVN + kc + lc);
        Qs[lc+0][lr] = qv.x; Qs[lc+1][lr] = qv.y; Qs[lc+2][lr] = qv.z; Qs[lc+3][lr] = qv.w;
        float4 kv = make_float4(0.f, 0.f, 0.f, 0.f);
        if (k0 + lr < SS) kv = *(const float4*)(Kbase + (size_t)(k0 + lr) * QKVN + kc + lc);
        Ks[lc+0][lr] = kv.x; Ks[lc+1][lr] = kv.y; Ks[lc+2][lr] = kv.z; Ks[lc+3][lr] = kv.w;
        __syncthreads();
        #pragma unroll
        for (int k = 0; k < 16; k++) {
            float qr[4], kr[4];
            *(float4*)qr = *(const float4*)&Qs[k][ty * 4];
            *(float4*)kr = *(const float4*)&Ks[k][tx * 4];
            #pragma unroll
            for (int i = 0; i < 4; i++)
                #pragma unroll
                for (int j = 0; j < 4; j++)
                    acc[i][j] = fmaf(qr[i], kr[j], acc[i][j]);
        }
        __syncthreads();
    }
    float* Sp = Sc + (size_t)bh * SS * SS;
    #pragma unroll
    for (int i = 0; i < 4; i++) {
        int qq = q0 + ty * 4 + i;
        if (qq >= SS) continue;
        #pragma unroll
        for (int j = 0; j < 4; j++) {
            int kk = k0 + tx * 4 + j;
            if (kk < SS) Sp[(size_t)qq * SS + kk] = acc[i][j] * 0.125f;
        }
    }
}

__global__ __launch_bounds__(256) void softmax_k(float* __restrict__ Sc) {
    float* p = Sc + (size_t)blockIdx.x * SS;
    int tid = threadIdx.x;
    float m = -INFINITY;
    for (int i = tid; i < SS; i += 256) m = fmaxf(m, p[i]);
    m = blk_max256(m);
    float sum = 0.f;
    for (int i = tid; i < SS; i += 256) {
        float e = expf(p[i] - m);
        p[i] = e;
        sum += e;
    }
    sum = blk_sum256(sum);
    float inv = 1.0f / sum;
    for (int i = tid; i < SS; i += 256) p[i] *= inv;
}

__global__ __launch_bounds__(256) void attn_pv_k(
    const float* __restrict__ QKV, const float* __restrict__ P,
    bf16* __restrict__ Oh, bf16* __restrict__ Ol) {
    int bh = blockIdx.y;
    int b = bh / HH, h = bh % HH;
    int q0 = blockIdx.x * 64;
    __shared__ float Ps[64][17];
    __shared__ float Vs[16][64];
    int tid = threadIdx.x;
    int tx = tid & 15, ty = tid >> 4;
    int pr = tid >> 2, pc0 = (tid & 3) * 4;
    int vr = tid >> 4, vc = (tid & 15) * 4;
    const float* Pp = P + (size_t)bh * SS * SS;
    const float* Vp = QKV + (size_t)b * SS * QKVN + 2 * DD + h * 64;
    float acc[4][4];
    #pragma unroll
    for (int i = 0; i < 4; i++)
        #pragma unroll
        for (int j = 0; j < 4; j++) acc[i][j] = 0.f;

    for (int k0 = 0; k0 < SS; k0 += 16) {
        int qq = q0 + pr;
        #pragma unroll
        for (int c = 0; c < 4; c++) {
            int kk = k0 + pc0 + c;
            Ps[pr][pc0 + c] = (qq < SS && kk < SS) ? Pp[(size_t)qq * SS + kk] : 0.f;
        }
        float4 vv = make_float4(0.f, 0.f, 0.f, 0.f);
        if (k0 + vr < SS) vv = *(const float4*)(Vp + (size_t)(k0 + vr) * QKVN + vc);
        *(float4*)&Vs[vr][vc] = vv;
        __syncthreads();
        #pragma unroll
        for (int k = 0; k < 16; k++) {
            float pv[4];
            #pragma unroll
            for (int i = 0; i < 4; i++) pv[i] = Ps[ty * 4 + i][k];
            float4 vvv = *(const float4*)&Vs[k][tx * 4];
            float vr4[4] = {vvv.x, vvv.y, vvv.z, vvv.w};
            #pragma unroll
            for (int i = 0; i < 4; i++)
                #pragma unroll
                for (int j = 0; j < 4; j++)
                    acc[i][j] = fmaf(pv[i], vr4[j], acc[i][j]);
        }
        __syncthreads();
    }
    #pragma unroll
    for (int i = 0; i < 4; i++) {
        int qq = q0 + ty * 4 + i;
        if (qq >= SS) continue;
        size_t off = (size_t)(b * SS + qq) * DD + h * 64 + tx * 4;
        uint32_t h01, l01, h23, l23;
        split_pair(acc[i][0], acc[i][1], h01, l01);
        split_pair(acc[i][2], acc[i][3], h23, l23);
        uint32_t* ph = (uint32_t*)(Oh + off);
        uint32_t* pl = (uint32_t*)(Ol + off);
        ph[0] = h01; ph[1] = h23;
        pl[0] = l01; pl[1] = l23;
    }
}

// ----------------------------------------------------------------------------
// Host orchestration
// ----------------------------------------------------------------------------
extern "C" void kernel_launch(void* const* d_in, const int* in_sizes, int n_in,
                              void* d_out, int out_size) {
    const int*   x      = (const int*)d_in[0];
    const float* emb    = (const float*)d_in[1];
    const float* attn_w = (const float*)d_in[2];
    const float* attn_b = (const float*)d_in[3];
    const float* ln_a   = (const float*)d_in[4];
    const float* ln_b   = (const float*)d_in[5];
    const float* w1     = (const float*)d_in[6];
    const float* b1     = (const float*)d_in[7];
    const float* w2     = (const float*)d_in[8];
    const float* b2     = (const float*)d_in[9];
    const float* na     = (const float*)d_in[10];
    const float* nb     = (const float*)d_in[11];
    float* out = (float*)d_out;

    float *h, *qkv, *s;
    bf16 *yh, *yl, *oh, *ol, *fh, *fl;
    bf16 *wqh, *wql, *woh, *wol, *w1h, *w1l, *w2h, *w2l;
    cudaGetSymbolAddress((void**)&h, g_h);
    cudaGetSymbolAddress((void**)&qkv, g_qkv);
    cudaGetSymbolAddress((void**)&s, g_s);
    cudaGetSymbolAddress((void**)&yh, g_yh);
    cudaGetSymbolAddress((void**)&yl, g_yl);
    cudaGetSymbolAddress((void**)&oh, g_oh);
    cudaGetSymbolAddress((void**)&ol, g_ol);
    cudaGetSymbolAddress((void**)&fh, g_fh);
    cudaGetSymbolAddress((void**)&fl, g_fl);
    cudaGetSymbolAddress((void**)&wqh, g_wqkvh);
    cudaGetSymbolAddress((void**)&wql, g_wqkvl);
    cudaGetSymbolAddress((void**)&woh, g_woh);
    cudaGetSymbolAddress((void**)&wol, g_wol);
    cudaGetSymbolAddress((void**)&w1h, g_w1h);
    cudaGetSymbolAddress((void**)&w1l, g_w1l);
    cudaGetSymbolAddress((void**)&w2h, g_w2h);
    cudaGetSymbolAddress((void**)&w2l, g_w2l);

    cudaFuncSetAttribute(gemm_k<0>, cudaFuncAttributeMaxDynamicSharedMemorySize, GEMM_SMEM);
    cudaFuncSetAttribute(gemm_k<1>, cudaFuncAttributeMaxDynamicSharedMemorySize, GEMM_SMEM);
    cudaFuncSetAttribute(gemm_k<2>, cudaFuncAttributeMaxDynamicSharedMemorySize, GEMM_SMEM);

    // weight transpose-convert (every call; weights are inputs)
    dim3 cb(32, 8);
    for (int l = 0; l < LL; l++) {
        for (int t = 0; t < 3; t++)
            convt_k<<<dim3(DD/32, DD/32), cb>>>(
                attn_w + ((size_t)(l*4 + t))*DD*DD,
                wqh + ((size_t)(l*3 + t))*DD*DD, wql + ((size_t)(l*3 + t))*DD*DD, DD, DD);
        convt_k<<<dim3(DD/32, DD/32), cb>>>(
            attn_w + ((size_t)(l*4 + 3))*DD*DD,
            woh + (size_t)l*DD*DD, wol + (size_t)l*DD*DD, DD, DD);
        convt_k<<<dim3(FF/32, DD/32), cb>>>(
            w1 + (size_t)l*DD*FF, w1h + (size_t)l*FF*DD, w1l + (size_t)l*FF*DD, DD, FF);
        convt_k<<<dim3(DD/32, FF/32), cb>>>(
            w2 + (size_t)l*FF*DD, w2h + (size_t)l*DD*FF, w2l + (size_t)l*DD*FF, FF, DD);
    }

    embed_k<<<(MM * DD + 255) / 256, 256>>>(x, emb, h);

    dim3 gQKV(QKVN / 128, (MM + 127) / 128);
    dim3 gD(DD / 128, (MM + 127) / 128);
    dim3 gF(FF / 128, (MM + 127) / 128);
    dim3 gS(8, 8, BB * HH);
    dim3 gPV(8, BB * HH);

    for (int l = 0; l < LL; l++) {
        const float* Wb = attn_b + (size_t)l * 4 * DD;
        const float* la = ln_a + (size_t)l * 2 * DD;
        const float* lb = ln_b + (size_t)l * 2 * DD;

        // attention sublayer
        ln_split_k<<<MM, 256>>>(h, la, lb, yh, yl);
        gemm_k<0><<<gQKV, 256, GEMM_SMEM>>>(yh, yl,
            wqh + (size_t)l*QKVN*DD, wql + (size_t)l*QKVN*DD,
            Wb, qkv, nullptr, nullptr, MM, QKVN, DD);
        attn_scores_k<<<gS, 256>>>(qkv, s);
        softmax_k<<<BB * HH * SS, 256>>>(s);
        attn_pv_k<<<gPV, 256>>>(qkv, s, oh, ol);
        gemm_k<1><<<gD, 256, GEMM_SMEM>>>(oh, ol,
            woh + (size_t)l*DD*DD, wol + (size_t)l*DD*DD,
            Wb + 3*DD, h, nullptr, nullptr, MM, DD, DD);

        // feed-forward sublayer
        ln_split_k<<<MM, 256>>>(h, la + DD, lb + DD, yh, yl);
        gemm_k<2><<<gF, 256, GEMM_SMEM>>>(yh, yl,
            w1h + (size_t)l*FF*DD, w1l + (size_t)l*FF*DD,
            b1 + (size_t)l*FF, nullptr, fh, fl, MM, FF, DD);
        gemm_k<1><<<gD, 256, GEMM_SMEM>>>(fh, fl,
            w2h + (size_t)l*DD*FF, w2l + (size_t)l*DD*FF,
            b2 + (size_t)l*DD, h, nullptr, nullptr, MM, DD, FF);
    }

    layernorm_k<<<MM, 256>>>(h, na, nb, out);
}

// round 5
// speedup vs baseline: 2.0783x; 1.1046x over previous
#include <cuda_runtime.h>
#include <cuda_bf16.h>
#include <math.h>
#include <stdint.h>

#define BB 8
#define SS 500
#define DD 1024
#define HH 16
#define LL 4
#define FF 4096
#define MM (BB*SS)          // 4000
#define QKVN (3*DD)         // 3072
#define LN_EPS 1e-6f

typedef __nv_bfloat16 bf16;

// ----------------------------------------------------------------------------
// Scratch (device globals; allocation-free)
// ----------------------------------------------------------------------------
__device__ __align__(128) float g_h[(size_t)MM*DD];
__device__ __align__(128) float g_qkv[(size_t)MM*QKVN];
__device__ __align__(128) float g_s[(size_t)BB*HH*SS*SS];
__device__ __align__(128) bf16 g_yh[(size_t)MM*DD], g_yl[(size_t)MM*DD];
__device__ __align__(128) bf16 g_oh[(size_t)MM*DD], g_ol[(size_t)MM*DD];
__device__ __align__(128) bf16 g_fh[(size_t)MM*FF], g_fl[(size_t)MM*FF];
__device__ __align__(128) bf16 g_wqkvh[(size_t)LL*QKVN*DD], g_wqkvl[(size_t)LL*QKVN*DD];
__device__ __align__(128) bf16 g_woh[(size_t)LL*DD*DD],     g_wol[(size_t)LL*DD*DD];
__device__ __align__(128) bf16 g_w1h[(size_t)LL*FF*DD],     g_w1l[(size_t)LL*FF*DD];
__device__ __align__(128) bf16 g_w2h[(size_t)LL*DD*FF],     g_w2l[(size_t)LL*DD*FF];

// ----------------------------------------------------------------------------
// Helpers
// ----------------------------------------------------------------------------
__device__ __forceinline__ float blk_sum256(float v) {
    __shared__ float sh[8];
    #pragma unroll
    for (int o = 16; o > 0; o >>= 1) v += __shfl_down_sync(0xffffffffu, v, o);
    __syncthreads();
    if ((threadIdx.x & 31) == 0) sh[threadIdx.x >> 5] = v;
    __syncthreads();
    float t = 0.f;
    #pragma unroll
    for (int i = 0; i < 8; i++) t += sh[i];
    return t;
}
__device__ __forceinline__ float blk_max256(float v) {
    __shared__ float sh[8];
    #pragma unroll
    for (int o = 16; o > 0; o >>= 1) v = fmaxf(v, __shfl_down_sync(0xffffffffu, v, o));
    __syncthreads();
    if ((threadIdx.x & 31) == 0) sh[threadIdx.x >> 5] = v;
    __syncthreads();
    float t = -INFINITY;
    #pragma unroll
    for (int i = 0; i < 8; i++) t = fmaxf(t, sh[i]);
    return t;
}

__device__ __forceinline__ void cp16(uint32_t dst, const void* src, int sz) {
    asm volatile("cp.async.cg.shared.global [%0], [%1], 16, %2;\n"
                 :: "r"(dst), "l"(src), "r"(sz));
}
__device__ __forceinline__ void cp_commit() { asm volatile("cp.async.commit_group;\n"); }
template<int N> __device__ __forceinline__ void cp_wait() {
    asm volatile("cp.async.wait_group %0;\n" :: "n"(N));
}
__device__ __forceinline__ void mma16816(float* c, const uint32_t* a, const uint32_t* b) {
    asm volatile("mma.sync.aligned.m16n8k16.row.col.f32.bf16.bf16.f32 "
        "{%0,%1,%2,%3},{%4,%5,%6,%7},{%8,%9},{%0,%1,%2,%3};\n"
        : "+f"(c[0]), "+f"(c[1]), "+f"(c[2]), "+f"(c[3])
        : "r"(a[0]), "r"(a[1]), "r"(a[2]), "r"(a[3]), "r"(b[0]), "r"(b[1]));
}
__device__ __forceinline__ void ldmx4(uint32_t* r, uint32_t addr) {
    asm volatile("ldmatrix.sync.aligned.m8n8.x4.shared.b16 {%0,%1,%2,%3}, [%4];"
        : "=r"(r[0]), "=r"(r[1]), "=r"(r[2]), "=r"(r[3]) : "r"(addr));
}
__device__ __forceinline__ uint32_t smem_u32(const void* p) {
    uint32_t a;
    asm("{ .reg .u64 t; cvta.to.shared.u64 t, %1; cvt.u32.u64 %0, t; }" : "=r"(a) : "l"(p));
    return a;
}
__device__ __forceinline__ void split_pair(float v0, float v1, uint32_t& hw, uint32_t& lw) {
    bf16 h0 = __float2bfloat16(v0), h1 = __float2bfloat16(v1);
    bf16 l0 = __float2bfloat16(v0 - __bfloat162float(h0));
    bf16 l1 = __float2bfloat16(v1 - __bfloat162float(h1));
    __nv_bfloat162 hh; hh.x = h0; hh.y = h1;
    __nv_bfloat162 ll; ll.x = l0; ll.y = l1;
    hw = *(uint32_t*)&hh; lw = *(uint32_t*)&ll;
}

// ----------------------------------------------------------------------------
// Embedding + positional encoding
// ----------------------------------------------------------------------------
__global__ void embed_k(const int* __restrict__ x, const float* __restrict__ emb,
                        float* __restrict__ h) {
    int idx = blockIdx.x * blockDim.x + threadIdx.x;
    if (idx >= MM * DD) return;
    int row = idx >> 10, d = idx & 1023;
    int s = row % SS;
    int tok = x[row];
    int i2 = d & ~1;
    float div = expf(-(float)i2 * (logf(10000.0f) / (float)DD));
    float ang = (float)s * div;
    float pe = (d & 1) ? cosf(ang) : sinf(ang);
    h[idx] = emb[(size_t)tok * DD + d] + pe;
}

// ----------------------------------------------------------------------------
// LayerNorm (torch: ddof=1, eps on std)
// ----------------------------------------------------------------------------
__global__ __launch_bounds__(256) void layernorm_k(
    const float* __restrict__ x, const float* __restrict__ a,
    const float* __restrict__ b, float* __restrict__ out) {
    int row = blockIdx.x;
    const float* xp = x + (size_t)row * DD;
    int t4 = threadIdx.x * 4;
    float4 xv = *(const float4*)(xp + t4);
    float mean = blk_sum256(xv.x + xv.y + xv.z + xv.w) * (1.0f / DD);
    float d0 = xv.x - mean, d1 = xv.y - mean, d2 = xv.z - mean, d3 = xv.w - mean;
    float var = blk_sum256(d0*d0 + d1*d1 + d2*d2 + d3*d3) * (1.0f / (DD - 1));
    float inv = 1.0f / (sqrtf(var) + LN_EPS);
    float4 av = *(const float4*)(a + t4);
    float4 bv = *(const float4*)(b + t4);
    float4 r;
    r.x = av.x * d0 * inv + bv.x; r.y = av.y * d1 * inv + bv.y;
    r.z = av.z * d2 * inv + bv.z; r.w = av.w * d3 * inv + bv.w;
    *(float4*)(out + (size_t)row * DD + t4) = r;
}

__global__ __launch_bounds__(256) void ln_split_k(
    const float* __restrict__ x, const float* __restrict__ a,
    const float* __restrict__ b, bf16* __restrict__ yh, bf16* __restrict__ yl) {
    int row = blockIdx.x;
    const float* xp = x + (size_t)row * DD;
    int t4 = threadIdx.x * 4;
    float4 xv = *(const float4*)(xp + t4);
    float mean = blk_sum256(xv.x + xv.y + xv.z + xv.w) * (1.0f / DD);
    float d0 = xv.x - mean, d1 = xv.y - mean, d2 = xv.z - mean, d3 = xv.w - mean;
    float var = blk_sum256(d0*d0 + d1*d1 + d2*d2 + d3*d3) * (1.0f / (DD - 1));
    float inv = 1.0f / (sqrtf(var) + LN_EPS);
    float4 av = *(const float4*)(a + t4);
    float4 bv = *(const float4*)(b + t4);
    float v0 = av.x * d0 * inv + bv.x, v1 = av.y * d1 * inv + bv.y;
    float v2 = av.z * d2 * inv + bv.z, v3 = av.w * d3 * inv + bv.w;
    uint32_t h01, l01, h23, l23;
    split_pair(v0, v1, h01, l01);
    split_pair(v2, v3, h23, l23);
    uint32_t* ph = (uint32_t*)(yh + (size_t)row * DD + t4);
    uint32_t* pl = (uint32_t*)(yl + (size_t)row * DD + t4);
    ph[0] = h01; ph[1] = h23; pl[0] = l01; pl[1] = l23;
}

// ----------------------------------------------------------------------------
// Weight transpose + hi/lo bf16 conversion: W[K][N] -> T[N][K]
// ----------------------------------------------------------------------------
__global__ void convt_k(const float* __restrict__ W, bf16* __restrict__ Th,
                        bf16* __restrict__ Tl, int K, int N) {
    __shared__ float t[32][33];
    int n0 = blockIdx.x * 32, k0 = blockIdx.y * 32;
    int tx = threadIdx.x, ty = threadIdx.y;
    #pragma unroll
    for (int i = ty; i < 32; i += 8) t[i][tx] = W[(size_t)(k0 + i) * N + n0 + tx];
    __syncthreads();
    #pragma unroll
    for (int i = ty; i < 32; i += 8) {
        float v = t[tx][i];
        bf16 h = __float2bfloat16(v);
        Th[(size_t)(n0 + i) * K + k0 + tx] = h;
        Tl[(size_t)(n0 + i) * K + k0 + tx] = __float2bfloat16(v - __bfloat162float(h));
    }
}

// ----------------------------------------------------------------------------
// bf16x3 GEMM via mma.sync + ldmatrix:  C[M,N] = A[M,K] @ B^T[N,K]
// 128x128 CTA tile, BK=64, 2-stage cp.async, 8 warps of 32x64.
// Smem per stage: AH|AL|BH|BL each 128x64 bf16 (16KB), SW128 swizzle. 64KB/stage.
// MODE 0: Cf = acc+bias | MODE 1: Cf += acc+bias | MODE 2: relu->split bf16
// ----------------------------------------------------------------------------
#define AH_B 0
#define AL_B 16384
#define BH_B 32768
#define BL_B 49152
#define STAGE_B 65536
#define GEMM_SMEM (2*STAGE_B)

__device__ __forceinline__ uint32_t swz128(uint32_t off) { return off ^ ((off >> 3) & 0x70); }

template<int MODE>
__global__ __launch_bounds__(256) void tgemm_k(
    const bf16* __restrict__ Ah, const bf16* __restrict__ Al,
    const bf16* __restrict__ Bh, const bf16* __restrict__ Bl,
    const float* __restrict__ bias, float* __restrict__ Cf,
    bf16* __restrict__ Oh, bf16* __restrict__ Ol,
    int M, int N, int K) {
    extern __shared__ __align__(1024) char smem[];
    const uint32_t sb = smem_u32(smem);
    const int tid = threadIdx.x;
    const int lane = tid & 31, wid = tid >> 5;
    const int wm = wid >> 1, wn = wid & 1;         // warp tile 32(M) x 64(N)
    const int bm = blockIdx.y * 128;
    const int bn = blockIdx.x * 128;
    const int lr = lane & 15, lh = lane >> 4;      // ldmatrix row / k-half
    const int g = lane >> 2, tig = lane & 3;

    float acc[2][8][4];
    #pragma unroll
    for (int i = 0; i < 2; i++)
        #pragma unroll
        for (int j = 0; j < 8; j++)
            #pragma unroll
            for (int r = 0; r < 4; r++) acc[i][j][r] = 0.f;

    const int nc = K >> 6;

    // Each stage: 128 rows x 128B per array; thread covers 4 (row,u) slots per array.
    #define PF(stg, kof)                                                          \
    {                                                                             \
        uint32_t base = sb + (stg) * STAGE_B;                                     \
        _Pragma("unroll")                                                         \
        for (int j = 0; j < 4; j++) {                                             \
            int idx = tid + 256 * j;                                              \
            int row = idx >> 3, u = idx & 7;                                      \
            uint32_t doff = (uint32_t)(row * 128) + (uint32_t)(((u ^ (row & 7)) << 4)); \
            int gr = bm + row;                                                    \
            int sz = (gr < M) ? 16 : 0;                                           \
            int grc = (gr < M) ? gr : 0;                                          \
            cp16(base + AH_B + doff, Ah + (size_t)grc * K + (kof) + u * 8, sz);   \
            cp16(base + AL_B + doff, Al + (size_t)grc * K + (kof) + u * 8, sz);   \
            int gn = bn + row;                                                    \
            cp16(base + BH_B + doff, Bh + (size_t)gn * K + (kof) + u * 8, 16);    \
            cp16(base + BL_B + doff, Bl + (size_t)gn * K + (kof) + u * 8, 16);    \
        }                                                                         \
    }

    PF(0, 0);
    cp_commit();

    for (int i = 0; i < nc; i++) {
        if (i + 1 < nc) {
            PF((i + 1) & 1, (i + 1) * 64);
            cp_commit();
            cp_wait<1>();
        } else {
            cp_wait<0>();
        }
        __syncthreads();

        uint32_t base = sb + (i & 1) * STAGE_B;
        #pragma unroll
        for (int kq = 0; kq < 4; kq++) {
            uint32_t fah[2][4], fal[2][4], fbh[4][4], fbl[4][4];
            #pragma unroll
            for (int mt = 0; mt < 2; mt++) {
                int row = wm * 32 + mt * 16 + lr;
                uint32_t chunk = (uint32_t)(kq * 2 + lh);
                uint32_t off = (uint32_t)(row * 128) + (((chunk ^ (uint32_t)(row & 7)) << 4));
                ldmx4(fah[mt], base + AH_B + off);
                ldmx4(fal[mt], base + AL_B + off);
            }
            #pragma unroll
            for (int j = 0; j < 4; j++) {
                int row = wn * 64 + j * 16 + lr;
                uint32_t chunk = (uint32_t)(kq * 2 + lh);
                uint32_t off = (uint32_t)(row * 128) + (((chunk ^ (uint32_t)(row & 7)) << 4));
                ldmx4(fbh[j], base + BH_B + off);
                ldmx4(fbl[j], base + BL_B + off);
            }
            #pragma unroll
            for (int mt = 0; mt < 2; mt++)
                #pragma unroll
                for (int nt = 0; nt < 8; nt++) {
                    int j = nt >> 1, sel = nt & 1;
                    uint32_t bhh[2] = { fbh[j][sel], fbh[j][sel + 2] };
                    uint32_t bll[2] = { fbl[j][sel], fbl[j][sel + 2] };
                    mma16816(acc[mt][nt], fah[mt], bhh);
                    mma16816(acc[mt][nt], fah[mt], bll);
                    mma16816(acc[mt][nt], fal[mt], bhh);
                }
        }
        __syncthreads();
    }

    // epilogue
    #pragma unroll
    for (int mt = 0; mt < 2; mt++) {
        #pragma unroll
        for (int nt = 0; nt < 8; nt++) {
            int c = bn + wn * 64 + nt * 8 + tig * 2;
            float bx = bias[c], by = bias[c + 1];
            #pragma unroll
            for (int half = 0; half < 2; half++) {
                int r = bm + wm * 32 + mt * 16 + g + half * 8;
                if (r >= M) continue;
                float v0 = acc[mt][nt][half * 2 + 0] + bx;
                float v1 = acc[mt][nt][half * 2 + 1] + by;
                if (MODE == 1) {
                    float2 old = *(float2*)(Cf + (size_t)r * N + c);
                    v0 += old.x; v1 += old.y;
                    float2 o; o.x = v0; o.y = v1;
                    *(float2*)(Cf + (size_t)r * N + c) = o;
                } else if (MODE == 2) {
                    v0 = fmaxf(v0, 0.f); v1 = fmaxf(v1, 0.f);
                    uint32_t hw, lw;
                    split_pair(v0, v1, hw, lw);
                    *(uint32_t*)(Oh + (size_t)r * N + c) = hw;
                    *(uint32_t*)(Ol + (size_t)r * N + c) = lw;
                } else {
                    float2 o; o.x = v0; o.y = v1;
                    *(float2*)(Cf + (size_t)r * N + c) = o;
                }
            }
        }
    }
    #undef PF
}

// ----------------------------------------------------------------------------
// Attention (fp32): scores, softmax, PV (PV writes hi/lo bf16)
// ----------------------------------------------------------------------------
__global__ __launch_bounds__(256) void attn_scores_k(
    const float* __restrict__ QKV, float* __restrict__ Sc) {
    int bh = blockIdx.z;
    int b = bh / HH, h = bh % HH;
    int q0 = blockIdx.y * 64, k0 = blockIdx.x * 64;
    __shared__ float Qs[16][64];
    __shared__ float Ks[16][64];
    int tid = threadIdx.x;
    int tx = tid & 15, ty = tid >> 4;
    int lr = tid >> 2, lc = (tid & 3) * 4;
    const float* Qbase = QKV + (size_t)b * SS * QKVN + h * 64;
    const float* Kbase = QKV + (size_t)b * SS * QKVN + DD + h * 64;
    float acc[4][4];
    #pragma unroll
    for (int i = 0; i < 4; i++)
        #pragma unroll
        for (int j = 0; j < 4; j++) acc[i][j] = 0.f;

    for (int kc = 0; kc < 64; kc += 16) {
        float4 qv = make_float4(0.f, 0.f, 0.f, 0.f);
        if (q0 + lr < SS) qv = *(const float4*)(Qbase + (size_t)(q0 + lr) * QKVN + kc + lc);
        Qs[lc+0][lr] = qv.x; Qs[lc+1][lr] = qv.y; Qs[lc+2][lr] = qv.z; Qs[lc+3][lr] = qv.w;
        float4 kv = make_float4(0.f, 0.f, 0.f, 0.f);
        if (k0 + lr < SS) kv = *(const float4*)(Kbase + (size_t)(k0 + lr) * QKVN + kc + lc);
        Ks[lc+0][lr] = kv.x; Ks[lc+1][lr] = kv.y; Ks[lc+2][lr] = kv.z; Ks[lc+3][lr] = kv.w;
        __syncthreads();
        #pragma unroll
        for (int k = 0; k < 16; k++) {
            float qr[4], kr[4];
            *(float4*)qr = *(const float4*)&Qs[k][ty * 4];
            *(float4*)kr = *(const float4*)&Ks[k][tx * 4];
            #pragma unroll
            for (int i = 0; i < 4; i++)
                #pragma unroll
                for (int j = 0; j < 4; j++)
                    acc[i][j] = fmaf(qr[i], kr[j], acc[i][j]);
        }
        __syncthreads();
    }
    float* Sp = Sc + (size_t)bh * SS * SS;
    #pragma unroll
    for (int i = 0; i < 4; i++) {
        int qq = q0 + ty * 4 + i;
        if (qq >= SS) continue;
        #pragma unroll
        for (int j = 0; j < 4; j++) {
            int kk = k0 + tx * 4 + j;
            if (kk < SS) Sp[(size_t)qq * SS + kk] = acc[i][j] * 0.125f;
        }
    }
}

__global__ __launch_bounds__(256) void softmax_k(float* __restrict__ Sc) {
    float* p = Sc + (size_t)blockIdx.x * SS;
    int tid = threadIdx.x;
    float m = -INFINITY;
    for (int i = tid; i < SS; i += 256) m = fmaxf(m, p[i]);
    m = blk_max256(m);
    float sum = 0.f;
    for (int i = tid; i < SS; i += 256) {
        float e = expf(p[i] - m);
        p[i] = e;
        sum += e;
    }
    sum = blk_sum256(sum);
    float inv = 1.0f / sum;
    for (int i = tid; i < SS; i += 256) p[i] *= inv;
}

__global__ __launch_bounds__(256) void attn_pv_k(
    const float* __restrict__ QKV, const float* __restrict__ P,
    bf16* __restrict__ Oh, bf16* __restrict__ Ol) {
    int bh = blockIdx.y;
    int b = bh / HH, h = bh % HH;
    int q0 = blockIdx.x * 64;
    __shared__ float Ps[64][17];
    __shared__ float Vs[16][64];
    int tid = threadIdx.x;
    int tx = tid & 15, ty = tid >> 4;
    int pr = tid >> 2, pc0 = (tid & 3) * 4;
    int vr = tid >> 4, vc = (tid & 15) * 4;
    const float* Pp = P + (size_t)bh * SS * SS;
    const float* Vp = QKV + (size_t)b * SS * QKVN + 2 * DD + h * 64;
    float acc[4][4];
    #pragma unroll
    for (int i = 0; i < 4; i++)
        #pragma unroll
        for (int j = 0; j < 4; j++) acc[i][j] = 0.f;

    for (int k0 = 0; k0 < SS; k0 += 16) {
        int qq = q0 + pr;
        #pragma unroll
        for (int c = 0; c < 4; c++) {
            int kk = k0 + pc0 + c;
            Ps[pr][pc0 + c] = (qq < SS && kk < SS) ? Pp[(size_t)qq * SS + kk] : 0.f;
        }
        float4 vv = make_float4(0.f, 0.f, 0.f, 0.f);
        if (k0 + vr < SS) vv = *(const float4*)(Vp + (size_t)(k0 + vr) * QKVN + vc);
        *(float4*)&Vs[vr][vc] = vv;
        __syncthreads();
        #pragma unroll
        for (int k = 0; k < 16; k++) {
            float pv[4];
            #pragma unroll
            for (int i = 0; i < 4; i++) pv[i] = Ps[ty * 4 + i][k];
            float4 vvv = *(const float4*)&Vs[k][tx * 4];
            float vr4[4] = {vvv.x, vvv.y, vvv.z, vvv.w};
            #pragma unroll
            for (int i = 0; i < 4; i++)
                #pragma unroll
                for (int j = 0; j < 4; j++)
                    acc[i][j] = fmaf(pv[i], vr4[j], acc[i][j]);
        }
        __syncthreads();
    }
    #pragma unroll
    for (int i = 0; i < 4; i++) {
        int qq = q0 + ty * 4 + i;
        if (qq >= SS) continue;
        size_t off = (size_t)(b * SS + qq) * DD + h * 64 + tx * 4;
        uint32_t h01, l01, h23, l23;
        split_pair(acc[i][0], acc[i][1], h01, l01);
        split_pair(acc[i][2], acc[i][3], h23, l23);
        uint32_t* ph = (uint32_t*)(Oh + off);
        uint32_t* pl = (uint32_t*)(Ol + off);
        ph[0] = h01; ph[1] = h23;
        pl[0] = l01; pl[1] = l23;
    }
}

// ----------------------------------------------------------------------------
// Host orchestration
// ----------------------------------------------------------------------------
extern "C" void kernel_launch(void* const* d_in, const int* in_sizes, int n_in,
                              void* d_out, int out_size) {
    const int*   x      = (const int*)d_in[0];
    const float* emb    = (const float*)d_in[1];
    const float* attn_w = (const float*)d_in[2];
    const float* attn_b = (const float*)d_in[3];
    const float* ln_a   = (const float*)d_in[4];
    const float* ln_b   = (const float*)d_in[5];
    const float* w1     = (const float*)d_in[6];
    const float* b1     = (const float*)d_in[7];
    const float* w2     = (const float*)d_in[8];
    const float* b2     = (const float*)d_in[9];
    const float* na     = (const float*)d_in[10];
    const float* nb     = (const float*)d_in[11];
    float* out = (float*)d_out;

    float *h, *qkv, *s;
    bf16 *yh, *yl, *oh, *ol, *fh, *fl;
    bf16 *wqh, *wql, *woh, *wol, *w1h, *w1l, *w2h, *w2l;
    cudaGetSymbolAddress((void**)&h, g_h);
    cudaGetSymbolAddress((void**)&qkv, g_qkv);
    cudaGetSymbolAddress((void**)&s, g_s);
    cudaGetSymbolAddress((void**)&yh, g_yh);
    cudaGetSymbolAddress((void**)&yl, g_yl);
    cudaGetSymbolAddress((void**)&oh, g_oh);
    cudaGetSymbolAddress((void**)&ol, g_ol);
    cudaGetSymbolAddress((void**)&fh, g_fh);
    cudaGetSymbolAddress((void**)&fl, g_fl);
    cudaGetSymbolAddress((void**)&wqh, g_wqkvh);
    cudaGetSymbolAddress((void**)&wql, g_wqkvl);
    cudaGetSymbolAddress((void**)&woh, g_woh);
    cudaGetSymbolAddress((void**)&wol, g_wol);
    cudaGetSymbolAddress((void**)&w1h, g_w1h);
    cudaGetSymbolAddress((void**)&w1l, g_w1l);
    cudaGetSymbolAddress((void**)&w2h, g_w2h);
    cudaGetSymbolAddress((void**)&w2l, g_w2l);

    cudaFuncSetAttribute(tgemm_k<0>, cudaFuncAttributeMaxDynamicSharedMemorySize, GEMM_SMEM);
    cudaFuncSetAttribute(tgemm_k<1>, cudaFuncAttributeMaxDynamicSharedMemorySize, GEMM_SMEM);
    cudaFuncSetAttribute(tgemm_k<2>, cudaFuncAttributeMaxDynamicSharedMemorySize, GEMM_SMEM);

    // weight transpose-convert
    dim3 cb(32, 8);
    for (int l = 0; l < LL; l++) {
        for (int t = 0; t < 3; t++)
            convt_k<<<dim3(DD/32, DD/32), cb>>>(
                attn_w + ((size_t)(l*4 + t))*DD*DD,
                wqh + ((size_t)(l*3 + t))*DD*DD, wql + ((size_t)(l*3 + t))*DD*DD, DD, DD);
        convt_k<<<dim3(DD/32, DD/32), cb>>>(
            attn_w + ((size_t)(l*4 + 3))*DD*DD,
            woh + (size_t)l*DD*DD, wol + (size_t)l*DD*DD, DD, DD);
        convt_k<<<dim3(FF/32, DD/32), cb>>>(
            w1 + (size_t)l*DD*FF, w1h + (size_t)l*FF*DD, w1l + (size_t)l*FF*DD, DD, FF);
        convt_k<<<dim3(DD/32, FF/32), cb>>>(
            w2 + (size_t)l*FF*DD, w2h + (size_t)l*DD*FF, w2l + (size_t)l*DD*FF, FF, DD);
    }

    embed_k<<<(MM * DD + 255) / 256, 256>>>(x, emb, h);

    dim3 gQKV(QKVN / 128, (MM + 127) / 128);   // (24, 32)
    dim3 gD(DD / 128, (MM + 127) / 128);       // (8, 32)
    dim3 gF(FF / 128, (MM + 127) / 128);       // (32, 32)
    dim3 gS(8, 8, BB * HH);
    dim3 gPV(8, BB * HH);

    for (int l = 0; l < LL; l++) {
        const float* Wb = attn_b + (size_t)l * 4 * DD;
        const float* la = ln_a + (size_t)l * 2 * DD;
        const float* lb = ln_b + (size_t)l * 2 * DD;

        // attention sublayer
        ln_split_k<<<MM, 256>>>(h, la, lb, yh, yl);
        tgemm_k<0><<<gQKV, 256, GEMM_SMEM>>>(yh, yl,
            wqh + (size_t)l*QKVN*DD, wql + (size_t)l*QKVN*DD,
            Wb, qkv, nullptr, nullptr, MM, QKVN, DD);
        attn_scores_k<<<gS, 256>>>(qkv, s);
        softmax_k<<<BB * HH * SS, 256>>>(s);
        attn_pv_k<<<gPV, 256>>>(qkv, s, oh, ol);
        tgemm_k<1><<<gD, 256, GEMM_SMEM>>>(oh, ol,
            woh + (size_t)l*DD*DD, wol + (size_t)l*DD*DD,
            Wb + 3*DD, h, nullptr, nullptr, MM, DD, DD);

        // feed-forward sublayer
        ln_split_k<<<MM, 256>>>(h, la + DD, lb + DD, yh, yl);
        tgemm_k<2><<<gF, 256, GEMM_SMEM>>>(yh, yl,
            w1h + (size_t)l*FF*DD, w1l + (size_t)l*FF*DD,
            b1 + (size_t)l*FF, nullptr, fh, fl, MM, FF, DD);
        tgemm_k<1><<<gD, 256, GEMM_SMEM>>>(fh, fl,
            w2h + (size_t)l*DD*FF, w2l + (size_t)l*DD*FF,
            b2 + (size_t)l*DD, h, nullptr, nullptr, MM, DD, FF);
    }

    layernorm_k<<<MM, 256>>>(h, na, nb, out);
}

// round 8
// speedup vs baseline: 2.6837x; 1.2913x over previous
#include <cuda_runtime.h>
#include <cuda_bf16.h>
#include <cuda_fp16.h>
#include <math.h>
#include <stdint.h>

#define BB 8
#define SS 500
#define DD 1024
#define HH 16
#define LL 4
#define FF 4096
#define MM (BB*SS)          // 4000
#define QKVN (3*DD)         // 3072
#define LN_EPS 1e-6f

typedef __half f16;

// ----------------------------------------------------------------------------
// Scratch (device globals; allocation-free)
// ----------------------------------------------------------------------------
__device__ __align__(128) float g_h[(size_t)MM*DD];
__device__ __align__(128) float g_qkv[(size_t)MM*QKVN];
__device__ __align__(128) float g_s[(size_t)BB*HH*SS*SS];
__device__ __align__(128) f16 g_y[(size_t)MM*DD];
__device__ __align__(128) f16 g_o[(size_t)MM*DD];
__device__ __align__(128) f16 g_f[(size_t)MM*FF];
// transposed weights, hi/lo fp16, layout [N][K]
__device__ __align__(128) f16 g_wqkvh[(size_t)LL*QKVN*DD], g_wqkvl[(size_t)LL*QKVN*DD];
__device__ __align__(128) f16 g_woh[(size_t)LL*DD*DD],     g_wol[(size_t)LL*DD*DD];
__device__ __align__(128) f16 g_w1h[(size_t)LL*FF*DD],     g_w1l[(size_t)LL*FF*DD];
__device__ __align__(128) f16 g_w2h[(size_t)LL*DD*FF],     g_w2l[(size_t)LL*DD*FF];

// ----------------------------------------------------------------------------
// Helpers
// ----------------------------------------------------------------------------
__device__ __forceinline__ float blk_sum256(float v) {
    __shared__ float sh[8];
    #pragma unroll
    for (int o = 16; o > 0; o >>= 1) v += __shfl_down_sync(0xffffffffu, v, o);
    __syncthreads();
    if ((threadIdx.x & 31) == 0) sh[threadIdx.x >> 5] = v;
    __syncthreads();
    float t = 0.f;
    #pragma unroll
    for (int i = 0; i < 8; i++) t += sh[i];
    return t;
}
__device__ __forceinline__ float blk_max256(float v) {
    __shared__ float sh[8];
    #pragma unroll
    for (int o = 16; o > 0; o >>= 1) v = fmaxf(v, __shfl_down_sync(0xffffffffu, v, o));
    __syncthreads();
    if ((threadIdx.x & 31) == 0) sh[threadIdx.x >> 5] = v;
    __syncthreads();
    float t = -INFINITY;
    #pragma unroll
    for (int i = 0; i < 8; i++) t = fmaxf(t, sh[i]);
    return t;
}

__device__ __forceinline__ void cp16(uint32_t dst, const void* src, int sz) {
    asm volatile("cp.async.cg.shared.global [%0], [%1], 16, %2;\n"
                 :: "r"(dst), "l"(src), "r"(sz));
}
__device__ __forceinline__ void cp_commit() { asm volatile("cp.async.commit_group;\n"); }
template<int N> __device__ __forceinline__ void cp_wait() {
    asm volatile("cp.async.wait_group %0;\n" :: "n"(N));
}
__device__ __forceinline__ void mma16816(float* c, const uint32_t* a, const uint32_t* b) {
    asm volatile("mma.sync.aligned.m16n8k16.row.col.f32.f16.f16.f32 "
        "{%0,%1,%2,%3},{%4,%5,%6,%7},{%8,%9},{%0,%1,%2,%3};\n"
        : "+f"(c[0]), "+f"(c[1]), "+f"(c[2]), "+f"(c[3])
        : "r"(a[0]), "r"(a[1]), "r"(a[2]), "r"(a[3]), "r"(b[0]), "r"(b[1]));
}
__device__ __forceinline__ void ldmx4(uint32_t* r, uint32_t addr) {
    asm volatile("ldmatrix.sync.aligned.m8n8.x4.shared.b16 {%0,%1,%2,%3}, [%4];"
        : "=r"(r[0]), "=r"(r[1]), "=r"(r[2]), "=r"(r[3]) : "r"(addr));
}
__device__ __forceinline__ uint32_t smem_u32(const void* p) {
    uint32_t a;
    asm("{ .reg .u64 t; cvta.to.shared.u64 t, %1; cvt.u32.u64 %0, t; }" : "=r"(a) : "l"(p));
    return a;
}
__device__ __forceinline__ uint32_t pack2h(float a, float b) {
    __half2 p = __floats2half2_rn(a, b);
    return *(uint32_t*)&p;
}

// ----------------------------------------------------------------------------
// Embedding + positional encoding
// ----------------------------------------------------------------------------
__global__ void embed_k(const int* __restrict__ x, const float* __restrict__ emb,
                        float* __restrict__ h) {
    int idx = blockIdx.x * blockDim.x + threadIdx.x;
    if (idx >= MM * DD) return;
    int row = idx >> 10, d = idx & 1023;
    int s = row % SS;
    int tok = x[row];
    int i2 = d & ~1;
    float div = expf(-(float)i2 * (logf(10000.0f) / (float)DD));
    float ang = (float)s * div;
    float pe = (d & 1) ? cosf(ang) : sinf(ang);
    h[idx] = emb[(size_t)tok * DD + d] + pe;
}

// ----------------------------------------------------------------------------
// LayerNorm (torch: ddof=1, eps on std)
// ----------------------------------------------------------------------------
__global__ __launch_bounds__(256) void layernorm_k(
    const float* __restrict__ x, const float* __restrict__ a,
    const float* __restrict__ b, float* __restrict__ out) {
    int row = blockIdx.x;
    const float* xp = x + (size_t)row * DD;
    int t4 = threadIdx.x * 4;
    float4 xv = *(const float4*)(xp + t4);
    float mean = blk_sum256(xv.x + xv.y + xv.z + xv.w) * (1.0f / DD);
    float d0 = xv.x - mean, d1 = xv.y - mean, d2 = xv.z - mean, d3 = xv.w - mean;
    float var = blk_sum256(d0*d0 + d1*d1 + d2*d2 + d3*d3) * (1.0f / (DD - 1));
    float inv = 1.0f / (sqrtf(var) + LN_EPS);
    float4 av = *(const float4*)(a + t4);
    float4 bv = *(const float4*)(b + t4);
    float4 r;
    r.x = av.x * d0 * inv + bv.x; r.y = av.y * d1 * inv + bv.y;
    r.z = av.z * d2 * inv + bv.z; r.w = av.w * d3 * inv + bv.w;
    *(float4*)(out + (size_t)row * DD + t4) = r;
}

// LayerNorm -> fp16 output
__global__ __launch_bounds__(256) void ln_h_k(
    const float* __restrict__ x, const float* __restrict__ a,
    const float* __restrict__ b, f16* __restrict__ y) {
    int row = blockIdx.x;
    const float* xp = x + (size_t)row * DD;
    int t4 = threadIdx.x * 4;
    float4 xv = *(const float4*)(xp + t4);
    float mean = blk_sum256(xv.x + xv.y + xv.z + xv.w) * (1.0f / DD);
    float d0 = xv.x - mean, d1 = xv.y - mean, d2 = xv.z - mean, d3 = xv.w - mean;
    float var = blk_sum256(d0*d0 + d1*d1 + d2*d2 + d3*d3) * (1.0f / (DD - 1));
    float inv = 1.0f / (sqrtf(var) + LN_EPS);
    float4 av = *(const float4*)(a + t4);
    float4 bv = *(const float4*)(b + t4);
    uint32_t* py = (uint32_t*)(y + (size_t)row * DD + t4);
    py[0] = pack2h(av.x * d0 * inv + bv.x, av.y * d1 * inv + bv.y);
    py[1] = pack2h(av.z * d2 * inv + bv.z, av.w * d3 * inv + bv.w);
}

// ----------------------------------------------------------------------------
// Weight transpose + hi/lo fp16 conversion: W[K][N] -> T[N][K]
// ----------------------------------------------------------------------------
__global__ void convt_k(const float* __restrict__ W, f16* __restrict__ Th,
                        f16* __restrict__ Tl, int K, int N) {
    __shared__ float t[32][33];
    int n0 = blockIdx.x * 32, k0 = blockIdx.y * 32;
    int tx = threadIdx.x, ty = threadIdx.y;
    #pragma unroll
    for (int i = ty; i < 32; i += 8) t[i][tx] = W[(size_t)(k0 + i) * N + n0 + tx];
    __syncthreads();
    #pragma unroll
    for (int i = ty; i < 32; i += 8) {
        float v = t[tx][i];
        f16 h = __float2half_rn(v);
        Th[(size_t)(n0 + i) * K + k0 + tx] = h;
        Tl[(size_t)(n0 + i) * K + k0 + tx] = __float2half_rn(v - __half2float(h));
    }
}

// ----------------------------------------------------------------------------
// fp16x2 GEMM via mma.sync + ldmatrix:  C[M,N] = A[M,K] @ B^T[N,K]
// A single fp16 (activations), B = Bh + Bl fp16 (weights, 22-bit mantissa).
// 128x128 CTA tile, BK=64, 2-stage cp.async, 8 warps of 32x64.
// Smem per stage: A|BH|BL each 128x64 f16 (16KB), SW128 swizzle -> 48KB/stage.
// MODE 0: Cf = acc+bias | MODE 1: Cf += acc+bias | MODE 2: relu -> fp16
// ----------------------------------------------------------------------------
#define SA_B 0
#define BH_B 16384
#define BL_B 32768
#define STAGE_B 49152
#define GEMM_SMEM (2*STAGE_B)

template<int MODE>
__global__ __launch_bounds__(256) void tgemm_k(
    const f16* __restrict__ A,
    const f16* __restrict__ Bh, const f16* __restrict__ Bl,
    const float* __restrict__ bias, float* __restrict__ Cf,
    f16* __restrict__ Of,
    int M, int N, int K) {
    extern __shared__ __align__(1024) char smem[];
    const uint32_t sb = smem_u32(smem);
    const int tid = threadIdx.x;
    const int lane = tid & 31, wid = tid >> 5;
    const int wm = wid >> 1, wn = wid & 1;         // warp tile 32(M) x 64(N)
    const int bm = blockIdx.y * 128;
    const int bn = blockIdx.x * 128;
    const int lr = lane & 15, lh = lane >> 4;      // ldmatrix row / k-half
    const int g = lane >> 2, tig = lane & 3;

    float acc[2][8][4];
    #pragma unroll
    for (int i = 0; i < 2; i++)
        #pragma unroll
        for (int j = 0; j < 8; j++)
            #pragma unroll
            for (int r = 0; r < 4; r++) acc[i][j][r] = 0.f;

    const int nc = K >> 6;

    #define PF(stg, kof)                                                          \
    {                                                                             \
        uint32_t base = sb + (stg) * STAGE_B;                                     \
        _Pragma("unroll")                                                         \
        for (int j = 0; j < 4; j++) {                                             \
            int idx = tid + 256 * j;                                              \
            int row = idx >> 3, u = idx & 7;                                      \
            uint32_t doff = (uint32_t)(row * 128) + (uint32_t)(((u ^ (row & 7)) << 4)); \
            int gr = bm + row;                                                    \
            int sz = (gr < M) ? 16 : 0;                                           \
            int grc = (gr < M) ? gr : 0;                                          \
            cp16(base + SA_B + doff, A + (size_t)grc * K + (kof) + u * 8, sz);    \
            int gn = bn + row;                                                    \
            cp16(base + BH_B + doff, Bh + (size_t)gn * K + (kof) + u * 8, 16);    \
            cp16(base + BL_B + doff, Bl + (size_t)gn * K + (kof) + u * 8, 16);    \
        }                                                                         \
    }

    PF(0, 0);
    cp_commit();

    for (int i = 0; i < nc; i++) {
        if (i + 1 < nc) {
            PF((i + 1) & 1, (i + 1) * 64);
            cp_commit();
            cp_wait<1>();
        } else {
            cp_wait<0>();
        }
        __syncthreads();

        uint32_t base = sb + (i & 1) * STAGE_B;
        #pragma unroll
        for (int kq = 0; kq < 4; kq++) {
            uint32_t fa[2][4], fbh[4][4], fbl[4][4];
            #pragma unroll
            for (int mt = 0; mt < 2; mt++) {
                int row = wm * 32 + mt * 16 + lr;
                uint32_t chunk = (uint32_t)(kq * 2 + lh);
                uint32_t off = (uint32_t)(row * 128) + (((chunk ^ (uint32_t)(row & 7)) << 4));
                ldmx4(fa[mt], base + SA_B + off);
            }
            #pragma unroll
            for (int j = 0; j < 4; j++) {
                int row = wn * 64 + j * 16 + lr;
                uint32_t chunk = (uint32_t)(kq * 2 + lh);
                uint32_t off = (uint32_t)(row * 128) + (((chunk ^ (uint32_t)(row & 7)) << 4));
                ldmx4(fbh[j], base + BH_B + off);
                ldmx4(fbl[j], base + BL_B + off);
            }
            #pragma unroll
            for (int mt = 0; mt < 2; mt++)
                #pragma unroll
                for (int nt = 0; nt < 8; nt++) {
                    int j = nt >> 1, sel = nt & 1;
                    uint32_t bhh[2] = { fbh[j][sel], fbh[j][sel + 2] };
                    uint32_t bll[2] = { fbl[j][sel], fbl[j][sel + 2] };
                    mma16816(acc[mt][nt], fa[mt], bhh);
                    mma16816(acc[mt][nt], fa[mt], bll);
                }
        }
        __syncthreads();
    }

    // epilogue
    #pragma unroll
    for (int mt = 0; mt < 2; mt++) {
        #pragma unroll
        for (int nt = 0; nt < 8; nt++) {
            int c = bn + wn * 64 + nt * 8 + tig * 2;
            float bx = bias[c], by = bias[c + 1];
            #pragma unroll
            for (int half = 0; half < 2; half++) {
                int r = bm + wm * 32 + mt * 16 + g + half * 8;
                if (r >= M) continue;
                float v0 = acc[mt][nt][half * 2 + 0] + bx;
                float v1 = acc[mt][nt][half * 2 + 1] + by;
                if (MODE == 1) {
                    float2 old = *(float2*)(Cf + (size_t)r * N + c);
                    v0 += old.x; v1 += old.y;
                    float2 o; o.x = v0; o.y = v1;
                    *(float2*)(Cf + (size_t)r * N + c) = o;
                } else if (MODE == 2) {
                    v0 = fmaxf(v0, 0.f); v1 = fmaxf(v1, 0.f);
                    *(uint32_t*)(Of + (size_t)r * N + c) = pack2h(v0, v1);
                } else {
                    float2 o; o.x = v0; o.y = v1;
                    *(float2*)(Cf + (size_t)r * N + c) = o;
                }
            }
        }
    }
    #undef PF
}

// ----------------------------------------------------------------------------
// Attention (fp32): scores, softmax, PV (PV writes fp16)
// q at col 0, k at 1024, v at 2048 within qkv[M][3072]
// ----------------------------------------------------------------------------
__global__ __launch_bounds__(256) void attn_scores_k(
    const float* __restrict__ QKV, float* __restrict__ Sc) {
    int bh = blockIdx.z;
    int b = bh / HH, h = bh % HH;
    int q0 = blockIdx.y * 64, k0 = blockIdx.x * 64;
    __shared__ float Qs[16][64];
    __shared__ float Ks[16][64];
    int tid = threadIdx.x;
    int tx = tid & 15, ty = tid >> 4;
    int lr = tid >> 2, lc = (tid & 3) * 4;
    const float* Qbase = QKV + (size_t)b * SS * QKVN + h * 64;
    const float* Kbase = QKV + (size_t)b * SS * QKVN + DD + h * 64;
    float acc[4][4];
    #pragma unroll
    for (int i = 0; i < 4; i++)
        #pragma unroll
        for (int j = 0; j < 4; j++) acc[i][j] = 0.f;

    for (int kc = 0; kc < 64; kc += 16) {
        float4 qv = make_float4(0.f, 0.f, 0.f, 0.f);
        if (q0 + lr < SS) qv = *(const float4*)(Qbase + (size_t)(q0 + lr) * QKVN + kc + lc);
        Qs[lc+0][lr] = qv.x; Qs[lc+1][lr] = qv.y; Qs[lc+2][lr] = qv.z; Qs[lc+3][lr] = qv.w;
        float4 kv = make_float4(0.f, 0.f, 0.f, 0.f);
        if (k0 + lr < SS) kv = *(const float4*)(Kbase + (size_t)(k0 + lr) * QKVN + kc + lc);
        Ks[lc+0][lr] = kv.x; Ks[lc+1][lr] = kv.y; Ks[lc+2][lr] = kv.z; Ks[lc+3][lr] = kv.w;
        __syncthreads();
        #pragma unroll
        for (int k = 0; k < 16; k++) {
            float qr[4], kr[4];
            *(float4*)qr = *(const float4*)&Qs[k][ty * 4];
            *(float4*)kr = *(const float4*)&Ks[k][tx * 4];
            #pragma unroll
            for (int i = 0; i < 4; i++)
                #pragma unroll
                for (int j = 0; j < 4; j++)
                    acc[i][j] = fmaf(qr[i], kr[j], acc[i][j]);
        }
        __syncthreads();
    }
    float* Sp = Sc + (size_t)bh * SS * SS;
    #pragma unroll
    for (int i = 0; i < 4; i++) {
        int qq = q0 + ty * 4 + i;
        if (qq >= SS) continue;
        #pragma unroll
        for (int j = 0; j < 4; j++) {
            int kk = k0 + tx * 4 + j;
            if (kk < SS) Sp[(size_t)qq * SS + kk] = acc[i][j] * 0.125f;
        }
    }
}

__global__ __launch_bounds__(256) void softmax_k(float* __restrict__ Sc) {
    float* p = Sc + (size_t)blockIdx.x * SS;
    int tid = threadIdx.x;
    float m = -INFINITY;
    for (int i = tid; i < SS; i += 256) m = fmaxf(m, p[i]);
    m = blk_max256(m);
    float sum = 0.f;
    for (int i = tid; i < SS; i += 256) {
        float e = expf(p[i] - m);
        p[i] = e;
        sum += e;
    }
    sum = blk_sum256(sum);
    float inv = 1.0f / sum;
    for (int i = tid; i < SS; i += 256) p[i] *= inv;
}

__global__ __launch_bounds__(256) void attn_pv_k(
    const float* __restrict__ QKV, const float* __restrict__ P,
    f16* __restrict__ O) {
    int bh = blockIdx.y;
    int b = bh / HH, h = bh % HH;
    int q0 = blockIdx.x * 64;
    __shared__ float Ps[64][17];
    __shared__ float Vs[16][64];
    int tid = threadIdx.x;
    int tx = tid & 15, ty = tid >> 4;
    int pr = tid >> 2, pc0 = (tid & 3) * 4;
    int vr = tid >> 4, vc = (tid & 15) * 4;
    const float* Pp = P + (size_t)bh * SS * SS;
    const float* Vp = QKV + (size_t)b * SS * QKVN + 2 * DD + h * 64;
    float acc[4][4];
    #pragma unroll
    for (int i = 0; i < 4; i++)
        #pragma unroll
        for (int j = 0; j < 4; j++) acc[i][j] = 0.f;

    for (int k0 = 0; k0 < SS; k0 += 16) {
        int qq = q0 + pr;
        #pragma unroll
        for (int c = 0; c < 4; c++) {
            int kk = k0 + pc0 + c;
            Ps[pr][pc0 + c] = (qq < SS && kk < SS) ? Pp[(size_t)qq * SS + kk] : 0.f;
        }
        float4 vv = make_float4(0.f, 0.f, 0.f, 0.f);
        if (k0 + vr < SS) vv = *(const float4*)(Vp + (size_t)(k0 + vr) * QKVN + vc);
        *(float4*)&Vs[vr][vc] = vv;
        __syncthreads();
        #pragma unroll
        for (int k = 0; k < 16; k++) {
            float pv[4];
            #pragma unroll
            for (int i = 0; i < 4; i++) pv[i] = Ps[ty * 4 + i][k];
            float4 vvv = *(const float4*)&Vs[k][tx * 4];
            float vr4[4] = {vvv.x, vvv.y, vvv.z, vvv.w};
            #pragma unroll
            for (int i = 0; i < 4; i++)
                #pragma unroll
                for (int j = 0; j < 4; j++)
                    acc[i][j] = fmaf(pv[i], vr4[j], acc[i][j]);
        }
        __syncthreads();
    }
    #pragma unroll
    for (int i = 0; i < 4; i++) {
        int qq = q0 + ty * 4 + i;
        if (qq >= SS) continue;
        size_t off = (size_t)(b * SS + qq) * DD + h * 64 + tx * 4;
        uint32_t* po = (uint32_t*)(O + off);
        po[0] = pack2h(acc[i][0], acc[i][1]);
        po[1] = pack2h(acc[i][2], acc[i][3]);
    }
}

// ----------------------------------------------------------------------------
// Host orchestration
// ----------------------------------------------------------------------------
extern "C" void kernel_launch(void* const* d_in, const int* in_sizes, int n_in,
                              void* d_out, int out_size) {
    const int*   x      = (const int*)d_in[0];
    const float* emb    = (const float*)d_in[1];
    const float* attn_w = (const float*)d_in[2];
    const float* attn_b = (const float*)d_in[3];
    const float* ln_a   = (const float*)d_in[4];
    const float* ln_b   = (const float*)d_in[5];
    const float* w1     = (const float*)d_in[6];
    const float* b1     = (const float*)d_in[7];
    const float* w2     = (const float*)d_in[8];
    const float* b2     = (const float*)d_in[9];
    const float* na     = (const float*)d_in[10];
    const float* nb     = (const float*)d_in[11];
    float* out = (float*)d_out;

    float *h, *qkv, *s;
    f16 *y, *o, *f;
    f16 *wqh, *wql, *woh, *wol, *w1h, *w1l, *w2h, *w2l;
    cudaGetSymbolAddress((void**)&h, g_h);
    cudaGetSymbolAddress((void**)&qkv, g_qkv);
    cudaGetSymbolAddress((void**)&s, g_s);
    cudaGetSymbolAddress((void**)&y, g_y);
    cudaGetSymbolAddress((void**)&o, g_o);
    cudaGetSymbolAddress((void**)&f, g_f);
    cudaGetSymbolAddress((void**)&wqh, g_wqkvh);
    cudaGetSymbolAddress((void**)&wql, g_wqkvl);
    cudaGetSymbolAddress((void**)&woh, g_woh);
    cudaGetSymbolAddress((void**)&wol, g_wol);
    cudaGetSymbolAddress((void**)&w1h, g_w1h);
    cudaGetSymbolAddress((void**)&w1l, g_w1l);
    cudaGetSymbolAddress((void**)&w2h, g_w2h);
    cudaGetSymbolAddress((void**)&w2l, g_w2l);

    cudaFuncSetAttribute(tgemm_k<0>, cudaFuncAttributeMaxDynamicSharedMemorySize, GEMM_SMEM);
    cudaFuncSetAttribute(tgemm_k<1>, cudaFuncAttributeMaxDynamicSharedMemorySize, GEMM_SMEM);
    cudaFuncSetAttribute(tgemm_k<2>, cudaFuncAttributeMaxDynamicSharedMemorySize, GEMM_SMEM);

    // weight transpose-convert
    dim3 cb(32, 8);
    for (int l = 0; l < LL; l++) {
        for (int t = 0; t < 3; t++)
            convt_k<<<dim3(DD/32, DD/32), cb>>>(
                attn_w + ((size_t)(l*4 + t))*DD*DD,
                wqh + ((size_t)(l*3 + t))*DD*DD, wql + ((size_t)(l*3 + t))*DD*DD, DD, DD);
        convt_k<<<dim3(DD/32, DD/32), cb>>>(
            attn_w + ((size_t)(l*4 + 3))*DD*DD,
            woh + (size_t)l*DD*DD, wol + (size_t)l*DD*DD, DD, DD);
        convt_k<<<dim3(FF/32, DD/32), cb>>>(
            w1 + (size_t)l*DD*FF, w1h + (size_t)l*FF*DD, w1l + (size_t)l*FF*DD, DD, FF);
        convt_k<<<dim3(DD/32, FF/32), cb>>>(
            w2 + (size_t)l*FF*DD, w2h + (size_t)l*DD*FF, w2l + (size_t)l*DD*FF, FF, DD);
    }

    embed_k<<<(MM * DD + 255) / 256, 256>>>(x, emb, h);

    dim3 gQKV(QKVN / 128, (MM + 127) / 128);   // (24, 32)
    dim3 gD(DD / 128, (MM + 127) / 128);       // (8, 32)
    dim3 gF(FF / 128, (MM + 127) / 128);       // (32, 32)
    dim3 gS(8, 8, BB * HH);
    dim3 gPV(8, BB * HH);

    for (int l = 0; l < LL; l++) {
        const float* Wb = attn_b + (size_t)l * 4 * DD;
        const float* la = ln_a + (size_t)l * 2 * DD;
        const float* lb = ln_b + (size_t)l * 2 * DD;

        // attention sublayer
        ln_h_k<<<MM, 256>>>(h, la, lb, y);
        tgemm_k<0><<<gQKV, 256, GEMM_SMEM>>>(y,
            wqh + (size_t)l*QKVN*DD, wql + (size_t)l*QKVN*DD,
            Wb, qkv, nullptr, MM, QKVN, DD);
        attn_scores_k<<<gS, 256>>>(qkv, s);
        softmax_k<<<BB * HH * SS, 256>>>(s);
        attn_pv_k<<<gPV, 256>>>(qkv, s, o);
        tgemm_k<1><<<gD, 256, GEMM_SMEM>>>(o,
            woh + (size_t)l*DD*DD, wol + (size_t)l*DD*DD,
            Wb + 3*DD, h, nullptr, MM, DD, DD);

        // feed-forward sublayer
        ln_h_k<<<MM, 256>>>(h, la + DD, lb + DD, y);
        tgemm_k<2><<<gF, 256, GEMM_SMEM>>>(y,
            w1h + (size_t)l*FF*DD, w1l + (size_t)l*FF*DD,
            b1 + (size_t)l*FF, nullptr, f, MM, FF, DD);
        tgemm_k<1><<<gD, 256, GEMM_SMEM>>>(f,
            w2h + (size_t)l*DD*FF, w2l + (size_t)l*DD*FF,
            b2 + (size_t)l*DD, h, nullptr, MM, DD, FF);
    }

    layernorm_k<<<MM, 256>>>(h, na, nb, out);
}

// round 9
// speedup vs baseline: 3.8971x; 1.4521x over previous
#include <cuda_runtime.h>
#include <cuda_bf16.h>
#include <cuda_fp16.h>
#include <math.h>
#include <stdint.h>

#define BB 8
#define SS 500
#define DD 1024
#define HH 16
#define LL 4
#define FF 4096
#define MM (BB*SS)          // 4000
#define QKVN (3*DD)         // 3072
#define LN_EPS 1e-6f

typedef __half f16;

// ----------------------------------------------------------------------------
// Scratch (device globals; allocation-free)
// ----------------------------------------------------------------------------
__device__ __align__(128) float g_h[(size_t)MM*DD];
__device__ __align__(128) float g_qkv[(size_t)MM*QKVN];
__device__ __align__(128) f16 g_y[(size_t)MM*DD];
__device__ __align__(128) f16 g_o[(size_t)MM*DD];
__device__ __align__(128) f16 g_f[(size_t)MM*FF];
// transposed weights, hi/lo fp16, layout [N][K]
__device__ __align__(128) f16 g_wqkvh[(size_t)LL*QKVN*DD], g_wqkvl[(size_t)LL*QKVN*DD];
__device__ __align__(128) f16 g_woh[(size_t)LL*DD*DD],     g_wol[(size_t)LL*DD*DD];
__device__ __align__(128) f16 g_w1h[(size_t)LL*FF*DD],     g_w1l[(size_t)LL*FF*DD];
__device__ __align__(128) f16 g_w2h[(size_t)LL*DD*FF],     g_w2l[(size_t)LL*DD*FF];

// ----------------------------------------------------------------------------
// Helpers
// ----------------------------------------------------------------------------
__device__ __forceinline__ float blk_sum256(float v) {
    __shared__ float sh[8];
    #pragma unroll
    for (int o = 16; o > 0; o >>= 1) v += __shfl_down_sync(0xffffffffu, v, o);
    __syncthreads();
    if ((threadIdx.x & 31) == 0) sh[threadIdx.x >> 5] = v;
    __syncthreads();
    float t = 0.f;
    #pragma unroll
    for (int i = 0; i < 8; i++) t += sh[i];
    return t;
}

__device__ __forceinline__ void cp16(uint32_t dst, const void* src, int sz) {
    asm volatile("cp.async.cg.shared.global [%0], [%1], 16, %2;\n"
                 :: "r"(dst), "l"(src), "r"(sz));
}
__device__ __forceinline__ void cp_commit() { asm volatile("cp.async.commit_group;\n"); }
template<int N> __device__ __forceinline__ void cp_wait() {
    asm volatile("cp.async.wait_group %0;\n" :: "n"(N));
}
__device__ __forceinline__ void mma16816(float* c, const uint32_t* a, const uint32_t* b) {
    asm volatile("mma.sync.aligned.m16n8k16.row.col.f32.f16.f16.f32 "
        "{%0,%1,%2,%3},{%4,%5,%6,%7},{%8,%9},{%0,%1,%2,%3};\n"
        : "+f"(c[0]), "+f"(c[1]), "+f"(c[2]), "+f"(c[3])
        : "r"(a[0]), "r"(a[1]), "r"(a[2]), "r"(a[3]), "r"(b[0]), "r"(b[1]));
}
__device__ __forceinline__ void ldmx4(uint32_t* r, uint32_t addr) {
    asm volatile("ldmatrix.sync.aligned.m8n8.x4.shared.b16 {%0,%1,%2,%3}, [%4];"
        : "=r"(r[0]), "=r"(r[1]), "=r"(r[2]), "=r"(r[3]) : "r"(addr));
}
__device__ __forceinline__ void ldmx4t(uint32_t* r, uint32_t addr) {
    asm volatile("ldmatrix.sync.aligned.m8n8.x4.trans.shared.b16 {%0,%1,%2,%3}, [%4];"
        : "=r"(r[0]), "=r"(r[1]), "=r"(r[2]), "=r"(r[3]) : "r"(addr));
}
__device__ __forceinline__ uint32_t smem_u32(const void* p) {
    uint32_t a;
    asm("{ .reg .u64 t; cvta.to.shared.u64 t, %1; cvt.u32.u64 %0, t; }" : "=r"(a) : "l"(p));
    return a;
}
__device__ __forceinline__ uint32_t pack2h(float a, float b) {
    __half2 p = __floats2half2_rn(a, b);
    return *(uint32_t*)&p;
}
__device__ __forceinline__ void split4(float4 v, uint32_t& hA, uint32_t& hB,
                                       uint32_t& lA, uint32_t& lB) {
    f16 h0 = __float2half_rn(v.x), h1 = __float2half_rn(v.y);
    f16 h2 = __float2half_rn(v.z), h3 = __float2half_rn(v.w);
    __half2 a, b, c, d;
    a.x = h0; a.y = h1; b.x = h2; b.y = h3;
    c.x = __float2half_rn(v.x - __half2float(h0));
    c.y = __float2half_rn(v.y - __half2float(h1));
    d.x = __float2half_rn(v.z - __half2float(h2));
    d.y = __float2half_rn(v.w - __half2float(h3));
    hA = *(uint32_t*)&a; hB = *(uint32_t*)&b;
    lA = *(uint32_t*)&c; lB = *(uint32_t*)&d;
}

// ----------------------------------------------------------------------------
// Embedding + positional encoding
// ----------------------------------------------------------------------------
__global__ void embed_k(const int* __restrict__ x, const float* __restrict__ emb,
                        float* __restrict__ h) {
    int idx = blockIdx.x * blockDim.x + threadIdx.x;
    if (idx >= MM * DD) return;
    int row = idx >> 10, d = idx & 1023;
    int s = row % SS;
    int tok = x[row];
    int i2 = d & ~1;
    float div = expf(-(float)i2 * (logf(10000.0f) / (float)DD));
    float ang = (float)s * div;
    float pe = (d & 1) ? cosf(ang) : sinf(ang);
    h[idx] = emb[(size_t)tok * DD + d] + pe;
}

// ----------------------------------------------------------------------------
// LayerNorm (torch: ddof=1, eps on std)
// ----------------------------------------------------------------------------
__global__ __launch_bounds__(256) void layernorm_k(
    const float* __restrict__ x, const float* __restrict__ a,
    const float* __restrict__ b, float* __restrict__ out) {
    int row = blockIdx.x;
    const float* xp = x + (size_t)row * DD;
    int t4 = threadIdx.x * 4;
    float4 xv = *(const float4*)(xp + t4);
    float mean = blk_sum256(xv.x + xv.y + xv.z + xv.w) * (1.0f / DD);
    float d0 = xv.x - mean, d1 = xv.y - mean, d2 = xv.z - mean, d3 = xv.w - mean;
    float var = blk_sum256(d0*d0 + d1*d1 + d2*d2 + d3*d3) * (1.0f / (DD - 1));
    float inv = 1.0f / (sqrtf(var) + LN_EPS);
    float4 av = *(const float4*)(a + t4);
    float4 bv = *(const float4*)(b + t4);
    float4 r;
    r.x = av.x * d0 * inv + bv.x; r.y = av.y * d1 * inv + bv.y;
    r.z = av.z * d2 * inv + bv.z; r.w = av.w * d3 * inv + bv.w;
    *(float4*)(out + (size_t)row * DD + t4) = r;
}

// LayerNorm -> fp16 output
__global__ __launch_bounds__(256) void ln_h_k(
    const float* __restrict__ x, const float* __restrict__ a,
    const float* __restrict__ b, f16* __restrict__ y) {
    int row = blockIdx.x;
    const float* xp = x + (size_t)row * DD;
    int t4 = threadIdx.x * 4;
    float4 xv = *(const float4*)(xp + t4);
    float mean = blk_sum256(xv.x + xv.y + xv.z + xv.w) * (1.0f / DD);
    float d0 = xv.x - mean, d1 = xv.y - mean, d2 = xv.z - mean, d3 = xv.w - mean;
    float var = blk_sum256(d0*d0 + d1*d1 + d2*d2 + d3*d3) * (1.0f / (DD - 1));
    float inv = 1.0f / (sqrtf(var) + LN_EPS);
    float4 av = *(const float4*)(a + t4);
    float4 bv = *(const float4*)(b + t4);
    uint32_t* py = (uint32_t*)(y + (size_t)row * DD + t4);
    py[0] = pack2h(av.x * d0 * inv + bv.x, av.y * d1 * inv + bv.y);
    py[1] = pack2h(av.z * d2 * inv + bv.z, av.w * d3 * inv + bv.w);
}

// ----------------------------------------------------------------------------
// Weight transpose + hi/lo fp16 conversion: W[K][N] -> T[N][K]
// ----------------------------------------------------------------------------
__global__ void convt_k(const float* __restrict__ W, f16* __restrict__ Th,
                        f16* __restrict__ Tl, int K, int N) {
    __shared__ float t[32][33];
    int n0 = blockIdx.x * 32, k0 = blockIdx.y * 32;
    int tx = threadIdx.x, ty = threadIdx.y;
    #pragma unroll
    for (int i = ty; i < 32; i += 8) t[i][tx] = W[(size_t)(k0 + i) * N + n0 + tx];
    __syncthreads();
    #pragma unroll
    for (int i = ty; i < 32; i += 8) {
        float v = t[tx][i];
        f16 h = __float2half_rn(v);
        Th[(size_t)(n0 + i) * K + k0 + tx] = h;
        Tl[(size_t)(n0 + i) * K + k0 + tx] = __float2half_rn(v - __half2float(h));
    }
}

// ----------------------------------------------------------------------------
// fp16x2 GEMM via mma.sync + ldmatrix:  C[M,N] = A[M,K] @ B^T[N,K]
// ----------------------------------------------------------------------------
#define SA_B 0
#define BH_B 16384
#define BL_B 32768
#define STAGE_B 49152
#define GEMM_SMEM (2*STAGE_B)

template<int MODE>
__global__ __launch_bounds__(256) void tgemm_k(
    const f16* __restrict__ A,
    const f16* __restrict__ Bh, const f16* __restrict__ Bl,
    const float* __restrict__ bias, float* __restrict__ Cf,
    f16* __restrict__ Of,
    int M, int N, int K) {
    extern __shared__ __align__(1024) char smem[];
    const uint32_t sb = smem_u32(smem);
    const int tid = threadIdx.x;
    const int lane = tid & 31, wid = tid >> 5;
    const int wm = wid >> 1, wn = wid & 1;
    const int bm = blockIdx.y * 128;
    const int bn = blockIdx.x * 128;
    const int lr = lane & 15, lh = lane >> 4;
    const int g = lane >> 2, tig = lane & 3;

    float acc[2][8][4];
    #pragma unroll
    for (int i = 0; i < 2; i++)
        #pragma unroll
        for (int j = 0; j < 8; j++)
            #pragma unroll
            for (int r = 0; r < 4; r++) acc[i][j][r] = 0.f;

    const int nc = K >> 6;

    #define PF(stg, kof)                                                          \
    {                                                                             \
        uint32_t base = sb + (stg) * STAGE_B;                                     \
        _Pragma("unroll")                                                         \
        for (int j = 0; j < 4; j++) {                                             \
            int idx = tid + 256 * j;                                              \
            int row = idx >> 3, u = idx & 7;                                      \
            uint32_t doff = (uint32_t)(row * 128) + (uint32_t)(((u ^ (row & 7)) << 4)); \
            int gr = bm + row;                                                    \
            int sz = (gr < M) ? 16 : 0;                                           \
            int grc = (gr < M) ? gr : 0;                                          \
            cp16(base + SA_B + doff, A + (size_t)grc * K + (kof) + u * 8, sz);    \
            int gn = bn + row;                                                    \
            cp16(base + BH_B + doff, Bh + (size_t)gn * K + (kof) + u * 8, 16);    \
            cp16(base + BL_B + doff, Bl + (size_t)gn * K + (kof) + u * 8, 16);    \
        }                                                                         \
    }

    PF(0, 0);
    cp_commit();

    for (int i = 0; i < nc; i++) {
        if (i + 1 < nc) {
            PF((i + 1) & 1, (i + 1) * 64);
            cp_commit();
            cp_wait<1>();
        } else {
            cp_wait<0>();
        }
        __syncthreads();

        uint32_t base = sb + (i & 1) * STAGE_B;
        #pragma unroll
        for (int kq = 0; kq < 4; kq++) {
            uint32_t fa[2][4], fbh[4][4], fbl[4][4];
            #pragma unroll
            for (int mt = 0; mt < 2; mt++) {
                int row = wm * 32 + mt * 16 + lr;
                uint32_t chunk = (uint32_t)(kq * 2 + lh);
                uint32_t off = (uint32_t)(row * 128) + (((chunk ^ (uint32_t)(row & 7)) << 4));
                ldmx4(fa[mt], base + SA_B + off);
            }
            #pragma unroll
            for (int j = 0; j < 4; j++) {
                int row = wn * 64 + j * 16 + lr;
                uint32_t chunk = (uint32_t)(kq * 2 + lh);
                uint32_t off = (uint32_t)(row * 128) + (((chunk ^ (uint32_t)(row & 7)) << 4));
                ldmx4(fbh[j], base + BH_B + off);
                ldmx4(fbl[j], base + BL_B + off);
            }
            #pragma unroll
            for (int mt = 0; mt < 2; mt++)
                #pragma unroll
                for (int nt = 0; nt < 8; nt++) {
                    int j = nt >> 1, sel = nt & 1;
                    uint32_t bhh[2] = { fbh[j][sel], fbh[j][sel + 2] };
                    uint32_t bll[2] = { fbl[j][sel], fbl[j][sel + 2] };
                    mma16816(acc[mt][nt], fa[mt], bhh);
                    mma16816(acc[mt][nt], fa[mt], bll);
                }
        }
        __syncthreads();
    }

    #pragma unroll
    for (int mt = 0; mt < 2; mt++) {
        #pragma unroll
        for (int nt = 0; nt < 8; nt++) {
            int c = bn + wn * 64 + nt * 8 + tig * 2;
            float bx = bias[c], by = bias[c + 1];
            #pragma unroll
            for (int half = 0; half < 2; half++) {
                int r = bm + wm * 32 + mt * 16 + g + half * 8;
                if (r >= M) continue;
                float v0 = acc[mt][nt][half * 2 + 0] + bx;
                float v1 = acc[mt][nt][half * 2 + 1] + by;
                if (MODE == 1) {
                    float2 old = *(float2*)(Cf + (size_t)r * N + c);
                    v0 += old.x; v1 += old.y;
                    float2 o; o.x = v0; o.y = v1;
                    *(float2*)(Cf + (size_t)r * N + c) = o;
                } else if (MODE == 2) {
                    v0 = fmaxf(v0, 0.f); v1 = fmaxf(v1, 0.f);
                    *(uint32_t*)(Of + (size_t)r * N + c) = pack2h(v0, v1);
                } else {
                    float2 o; o.x = v0; o.y = v1;
                    *(float2*)(Cf + (size_t)r * N + c) = o;
                }
            }
        }
    }
    #undef PF
}

// ----------------------------------------------------------------------------
// Fused flash attention: per CTA one (b,h) x 64-q-row tile, 128 threads.
// Q,K fp16 hi/lo (3-term QK^T, fp32-accurate scores), online softmax fp32,
// P single fp16, V fp16 hi/lo. Output O fp16 [b,s,h*64+d].
// Smem 32KB: [0,16K) = Q hi/lo then V hi/lo (reused); [16K,32K) = K hi/lo.
// ----------------------------------------------------------------------------
__global__ __launch_bounds__(128) void flash_k(
    const float* __restrict__ QKV, f16* __restrict__ O) {
    __shared__ __align__(1024) char sm[32768];
    const uint32_t sQV = smem_u32(sm);
    const uint32_t sK  = sQV + 16384;
    const int tid = threadIdx.x, lane = tid & 31, wid = tid >> 5;
    const int lr = lane & 15, lh = lane >> 4;
    const int g = lane >> 2, tig = lane & 3;
    const int bh = blockIdx.y, b = bh >> 4, h = bh & 15;
    const int q0 = blockIdx.x * 64;
    const float* Qg = QKV + (size_t)b * SS * QKVN + h * 64;
    const float* Kg = Qg + DD;
    const float* Vg = Qg + 2 * DD;

    // load Q tile 64x64 fp32 -> hi/lo fp16 smem (swizzled 128B rows)
    #pragma unroll
    for (int j = 0; j < 8; j++) {
        int slot = tid + 128 * j;
        int row = slot >> 4, c4 = slot & 15;
        int qrow = q0 + row;
        float4 v = make_float4(0.f, 0.f, 0.f, 0.f);
        if (qrow < SS) v = *(const float4*)(Qg + (size_t)qrow * QKVN + c4 * 4);
        uint32_t hA, hB, lA, lB;
        split4(v, hA, hB, lA, lB);
        uint32_t off = (uint32_t)(row * 128) + ((((uint32_t)(c4 >> 1)) ^ (uint32_t)(row & 7)) << 4) + (c4 & 1) * 8;
        *(uint32_t*)(sm + off) = hA;          *(uint32_t*)(sm + off + 4) = hB;
        *(uint32_t*)(sm + 8192 + off) = lA;   *(uint32_t*)(sm + 8192 + off + 4) = lB;
    }
    __syncthreads();

    // extract Q fragments (per warp: rows wid*16..+15, 4 k16 chunks over DK=64)
    uint32_t qh[4][4], ql[4][4];
    #pragma unroll
    for (int kq = 0; kq < 4; kq++) {
        int row = wid * 16 + lr;
        uint32_t chunk = (uint32_t)(kq * 2 + lh);
        uint32_t off = (uint32_t)(row * 128) + ((chunk ^ (uint32_t)(row & 7)) << 4);
        ldmx4(qh[kq], sQV + off);
        ldmx4(ql[kq], sQV + 8192 + off);
    }

    float m0 = -1e30f, m1 = -1e30f, l0 = 0.f, l1 = 0.f;
    float ao[8][4];
    #pragma unroll
    for (int j = 0; j < 8; j++)
        #pragma unroll
        for (int r = 0; r < 4; r++) ao[j][r] = 0.f;

    for (int k0 = 0; k0 < SS; k0 += 64) {
        __syncthreads();   // previous compute done; Q frags extracted (first iter)
        // load K,V tiles 64x64 fp32 -> hi/lo fp16 smem
        #pragma unroll
        for (int j = 0; j < 8; j++) {
            int slot = tid + 128 * j;
            int row = slot >> 4, c4 = slot & 15;
            int krow = k0 + row;
            float4 kv = make_float4(0.f, 0.f, 0.f, 0.f);
            float4 vv = make_float4(0.f, 0.f, 0.f, 0.f);
            if (krow < SS) {
                kv = *(const float4*)(Kg + (size_t)krow * QKVN + c4 * 4);
                vv = *(const float4*)(Vg + (size_t)krow * QKVN + c4 * 4);
            }
            uint32_t off = (uint32_t)(row * 128) + ((((uint32_t)(c4 >> 1)) ^ (uint32_t)(row & 7)) << 4) + (c4 & 1) * 8;
            uint32_t hA, hB, lA, lB;
            split4(kv, hA, hB, lA, lB);
            *(uint32_t*)(sm + 16384 + off) = hA;  *(uint32_t*)(sm + 16384 + off + 4) = hB;
            *(uint32_t*)(sm + 24576 + off) = lA;  *(uint32_t*)(sm + 24576 + off + 4) = lB;
            split4(vv, hA, hB, lA, lB);
            *(uint32_t*)(sm + off) = hA;          *(uint32_t*)(sm + off + 4) = hB;
            *(uint32_t*)(sm + 8192 + off) = lA;   *(uint32_t*)(sm + 8192 + off + 4) = lB;
        }
        __syncthreads();

        // scores: S[16 x 64] per warp, 3-term hi/lo
        float s[8][4];
        #pragma unroll
        for (int nt = 0; nt < 8; nt++)
            #pragma unroll
            for (int r = 0; r < 4; r++) s[nt][r] = 0.f;
        #pragma unroll
        for (int kq = 0; kq < 4; kq++) {
            uint32_t fkh[4][4], fkl[4][4];
            #pragma unroll
            for (int j2 = 0; j2 < 4; j2++) {
                int row = j2 * 16 + lr;
                uint32_t chunk = (uint32_t)(kq * 2 + lh);
                uint32_t off = (uint32_t)(row * 128) + ((chunk ^ (uint32_t)(row & 7)) << 4);
                ldmx4(fkh[j2], sK + off);
                ldmx4(fkl[j2], sK + 8192 + off);
            }
            #pragma unroll
            for (int nt = 0; nt < 8; nt++) {
                int j2 = nt >> 1, sel = nt & 1;
                uint32_t bhh[2] = { fkh[j2][sel], fkh[j2][sel + 2] };
                uint32_t bll[2] = { fkl[j2][sel], fkl[j2][sel + 2] };
                mma16816(s[nt], qh[kq], bhh);
                mma16816(s[nt], qh[kq], bll);
                mma16816(s[nt], ql[kq], bhh);
            }
        }
        // scale + mask
        bool tail = (k0 + 64 > SS);
        #pragma unroll
        for (int nt = 0; nt < 8; nt++)
            #pragma unroll
            for (int r = 0; r < 4; r++) {
                s[nt][r] *= 0.125f;
                if (tail && (k0 + nt * 8 + tig * 2 + (r & 1)) >= SS) s[nt][r] = -1e30f;
            }
        // online softmax
        float mx0 = -1e30f, mx1 = -1e30f;
        #pragma unroll
        for (int nt = 0; nt < 8; nt++) {
            mx0 = fmaxf(mx0, fmaxf(s[nt][0], s[nt][1]));
            mx1 = fmaxf(mx1, fmaxf(s[nt][2], s[nt][3]));
        }
        mx0 = fmaxf(mx0, __shfl_xor_sync(0xffffffffu, mx0, 1));
        mx0 = fmaxf(mx0, __shfl_xor_sync(0xffffffffu, mx0, 2));
        mx1 = fmaxf(mx1, __shfl_xor_sync(0xffffffffu, mx1, 1));
        mx1 = fmaxf(mx1, __shfl_xor_sync(0xffffffffu, mx1, 2));
        float mn0 = fmaxf(m0, mx0), mn1 = fmaxf(m1, mx1);
        float sc0 = __expf(m0 - mn0), sc1 = __expf(m1 - mn1);
        m0 = mn0; m1 = mn1;
        float rs0 = 0.f, rs1 = 0.f;
        #pragma unroll
        for (int nt = 0; nt < 8; nt++) {
            s[nt][0] = __expf(s[nt][0] - m0); rs0 += s[nt][0];
            s[nt][1] = __expf(s[nt][1] - m0); rs0 += s[nt][1];
            s[nt][2] = __expf(s[nt][2] - m1); rs1 += s[nt][2];
            s[nt][3] = __expf(s[nt][3] - m1); rs1 += s[nt][3];
        }
        rs0 += __shfl_xor_sync(0xffffffffu, rs0, 1);
        rs0 += __shfl_xor_sync(0xffffffffu, rs0, 2);
        rs1 += __shfl_xor_sync(0xffffffffu, rs1, 1);
        rs1 += __shfl_xor_sync(0xffffffffu, rs1, 2);
        l0 = l0 * sc0 + rs0; l1 = l1 * sc1 + rs1;
        #pragma unroll
        for (int j = 0; j < 8; j++) {
            ao[j][0] *= sc0; ao[j][1] *= sc0;
            ao[j][2] *= sc1; ao[j][3] *= sc1;
        }
        // PV: P (fp16 from s regs) @ V (hi/lo via ldmatrix.trans)
        #pragma unroll
        for (int kc = 0; kc < 4; kc++) {
            uint32_t pa[4] = {
                pack2h(s[2*kc][0],   s[2*kc][1]),
                pack2h(s[2*kc][2],   s[2*kc][3]),
                pack2h(s[2*kc+1][0], s[2*kc+1][1]),
                pack2h(s[2*kc+1][2], s[2*kc+1][3]) };
            int vrow = kc * 16 + (lane & 7) + ((lane & 8) ? 8 : 0);
            #pragma unroll
            for (int dp = 0; dp < 4; dp++) {
                uint32_t u = (uint32_t)(dp * 2 + ((lane & 16) ? 1 : 0));
                uint32_t off = (uint32_t)(vrow * 128) + ((u ^ (uint32_t)(vrow & 7)) << 4);
                uint32_t fvh[4], fvl[4];
                ldmx4t(fvh, sQV + off);
                ldmx4t(fvl, sQV + 8192 + off);
                uint32_t b0h[2] = { fvh[0], fvh[1] }, b1h[2] = { fvh[2], fvh[3] };
                uint32_t b0l[2] = { fvl[0], fvl[1] }, b1l[2] = { fvl[2], fvl[3] };
                mma16816(ao[dp*2],     pa, b0h);
                mma16816(ao[dp*2],     pa, b0l);
                mma16816(ao[dp*2 + 1], pa, b1h);
                mma16816(ao[dp*2 + 1], pa, b1l);
            }
        }
    }

    // normalize + store O fp16
    float il0 = 1.f / l0, il1 = 1.f / l1;
    int r0 = q0 + wid * 16 + g, r1 = r0 + 8;
    #pragma unroll
    for (int j = 0; j < 8; j++) {
        int d = h * 64 + j * 8 + tig * 2;
        if (r0 < SS)
            *(uint32_t*)(O + (size_t)(b * SS + r0) * DD + d) = pack2h(ao[j][0] * il0, ao[j][1] * il0);
        if (r1 < SS)
            *(uint32_t*)(O + (size_t)(b * SS + r1) * DD + d) = pack2h(ao[j][2] * il1, ao[j][3] * il1);
    }
}

// ----------------------------------------------------------------------------
// Host orchestration
// ----------------------------------------------------------------------------
extern "C" void kernel_launch(void* const* d_in, const int* in_sizes, int n_in,
                              void* d_out, int out_size) {
    const int*   x      = (const int*)d_in[0];
    const float* emb    = (const float*)d_in[1];
    const float* attn_w = (const float*)d_in[2];
    const float* attn_b = (const float*)d_in[3];
    const float* ln_a   = (const float*)d_in[4];
    const float* ln_b   = (const float*)d_in[5];
    const float* w1     = (const float*)d_in[6];
    const float* b1     = (const float*)d_in[7];
    const float* w2     = (const float*)d_in[8];
    const float* b2     = (const float*)d_in[9];
    const float* na     = (const float*)d_in[10];
    const float* nb     = (const float*)d_in[11];
    float* out = (float*)d_out;

    float *h, *qkv;
    f16 *y, *o, *f;
    f16 *wqh, *wql, *woh, *wol, *w1h, *w1l, *w2h, *w2l;
    cudaGetSymbolAddress((void**)&h, g_h);
    cudaGetSymbolAddress((void**)&qkv, g_qkv);
    cudaGetSymbolAddress((void**)&y, g_y);
    cudaGetSymbolAddress((void**)&o, g_o);
    cudaGetSymbolAddress((void**)&f, g_f);
    cudaGetSymbolAddress((void**)&wqh, g_wqkvh);
    cudaGetSymbolAddress((void**)&wql, g_wqkvl);
    cudaGetSymbolAddress((void**)&woh, g_woh);
    cudaGetSymbolAddress((void**)&wol, g_wol);
    cudaGetSymbolAddress((void**)&w1h, g_w1h);
    cudaGetSymbolAddress((void**)&w1l, g_w1l);
    cudaGetSymbolAddress((void**)&w2h, g_w2h);
    cudaGetSymbolAddress((void**)&w2l, g_w2l);

    cudaFuncSetAttribute(tgemm_k<0>, cudaFuncAttributeMaxDynamicSharedMemorySize, GEMM_SMEM);
    cudaFuncSetAttribute(tgemm_k<1>, cudaFuncAttributeMaxDynamicSharedMemorySize, GEMM_SMEM);
    cudaFuncSetAttribute(tgemm_k<2>, cudaFuncAttributeMaxDynamicSharedMemorySize, GEMM_SMEM);

    // weight transpose-convert
    dim3 cb(32, 8);
    for (int l = 0; l < LL; l++) {
        for (int t = 0; t < 3; t++)
            convt_k<<<dim3(DD/32, DD/32), cb>>>(
                attn_w + ((size_t)(l*4 + t))*DD*DD,
                wqh + ((size_t)(l*3 + t))*DD*DD, wql + ((size_t)(l*3 + t))*DD*DD, DD, DD);
        convt_k<<<dim3(DD/32, DD/32), cb>>>(
            attn_w + ((size_t)(l*4 + 3))*DD*DD,
            woh + (size_t)l*DD*DD, wol + (size_t)l*DD*DD, DD, DD);
        convt_k<<<dim3(FF/32, DD/32), cb>>>(
            w1 + (size_t)l*DD*FF, w1h + (size_t)l*FF*DD, w1l + (size_t)l*FF*DD, DD, FF);
        convt_k<<<dim3(DD/32, FF/32), cb>>>(
            w2 + (size_t)l*FF*DD, w2h + (size_t)l*DD*FF, w2l + (size_t)l*DD*FF, FF, DD);
    }

    embed_k<<<(MM * DD + 255) / 256, 256>>>(x, emb, h);

    dim3 gQKV(QKVN / 128, (MM + 127) / 128);   // (24, 32)
    dim3 gD(DD / 128, (MM + 127) / 128);       // (8, 32)
    dim3 gF(FF / 128, (MM + 127) / 128);       // (32, 32)
    dim3 gFA(8, BB * HH);                      // (q-tiles, bh)

    for (int l = 0; l < LL; l++) {
        const float* Wb = attn_b + (size_t)l * 4 * DD;
        const float* la = ln_a + (size_t)l * 2 * DD;
        const float* lb = ln_b + (size_t)l * 2 * DD;

        // attention sublayer
        ln_h_k<<<MM, 256>>>(h, la, lb, y);
        tgemm_k<0><<<gQKV, 256, GEMM_SMEM>>>(y,
            wqh + (size_t)l*QKVN*DD, wql + (size_t)l*QKVN*DD,
            Wb, qkv, nullptr, MM, QKVN, DD);
        flash_k<<<gFA, 128>>>(qkv, o);
        tgemm_k<1><<<gD, 256, GEMM_SMEM>>>(o,
            woh + (size_t)l*DD*DD, wol + (size_t)l*DD*DD,
            Wb + 3*DD, h, nullptr, MM, DD, DD);

        // feed-forward sublayer
        ln_h_k<<<MM, 256>>>(h, la + DD, lb + DD, y);
        tgemm_k<2><<<gF, 256, GEMM_SMEM>>>(y,
            w1h + (size_t)l*FF*DD, w1l + (size_t)l*FF*DD,
            b1 + (size_t)l*FF, nullptr, f, MM, FF, DD);
        tgemm_k<1><<<gD, 256, GEMM_SMEM>>>(f,
            w2h + (size_t)l*DD*FF, w2l + (size_t)l*DD*FF,
            b2 + (size_t)l*DD, h, nullptr, MM, DD, FF);
    }

    layernorm_k<<<MM, 256>>>(h, na, nb, out);
}

// round 10
// speedup vs baseline: 6.5545x; 1.6819x over previous
#include <cuda_runtime.h>
#include <cuda_bf16.h>
#include <cuda_fp16.h>
#include <math.h>
#include <stdint.h>

#define BB 8
#define SS 500
#define DD 1024
#define HH 16
#define LL 4
#define FF 4096
#define MM (BB*SS)          // 4000
#define QKVN (3*DD)         // 3072
#define LN_EPS 1e-6f

typedef __half f16;

// ----------------------------------------------------------------------------
// Scratch (device globals; allocation-free)
// ----------------------------------------------------------------------------
__device__ __align__(128) float g_h[(size_t)MM*DD];
__device__ __align__(128) float g_qkv[(size_t)MM*QKVN];
__device__ __align__(128) f16 g_y[(size_t)MM*DD];
__device__ __align__(128) f16 g_o[(size_t)MM*DD];
__device__ __align__(128) f16 g_f[(size_t)MM*FF];
// transposed weights, fp16, layout [N][K]
__device__ __align__(128) f16 g_wqkv[(size_t)LL*QKVN*DD];
__device__ __align__(128) f16 g_wo[(size_t)LL*DD*DD];
__device__ __align__(128) f16 g_w1[(size_t)LL*FF*DD];
__device__ __align__(128) f16 g_w2[(size_t)LL*DD*FF];

// ----------------------------------------------------------------------------
// Helpers
// ----------------------------------------------------------------------------
__device__ __forceinline__ float blk_sum256(float v) {
    __shared__ float sh[8];
    #pragma unroll
    for (int o = 16; o > 0; o >>= 1) v += __shfl_down_sync(0xffffffffu, v, o);
    __syncthreads();
    if ((threadIdx.x & 31) == 0) sh[threadIdx.x >> 5] = v;
    __syncthreads();
    float t = 0.f;
    #pragma unroll
    for (int i = 0; i < 8; i++) t += sh[i];
    return t;
}

__device__ __forceinline__ void cp16(uint32_t dst, const void* src, int sz) {
    asm volatile("cp.async.cg.shared.global [%0], [%1], 16, %2;\n"
                 :: "r"(dst), "l"(src), "r"(sz));
}
__device__ __forceinline__ void cp_commit() { asm volatile("cp.async.commit_group;\n"); }
template<int N> __device__ __forceinline__ void cp_wait() {
    asm volatile("cp.async.wait_group %0;\n" :: "n"(N));
}
__device__ __forceinline__ void mma16816(float* c, const uint32_t* a, const uint32_t* b) {
    asm volatile("mma.sync.aligned.m16n8k16.row.col.f32.f16.f16.f32 "
        "{%0,%1,%2,%3},{%4,%5,%6,%7},{%8,%9},{%0,%1,%2,%3};\n"
        : "+f"(c[0]), "+f"(c[1]), "+f"(c[2]), "+f"(c[3])
        : "r"(a[0]), "r"(a[1]), "r"(a[2]), "r"(a[3]), "r"(b[0]), "r"(b[1]));
}
__device__ __forceinline__ void ldmx4(uint32_t* r, uint32_t addr) {
    asm volatile("ldmatrix.sync.aligned.m8n8.x4.shared.b16 {%0,%1,%2,%3}, [%4];"
        : "=r"(r[0]), "=r"(r[1]), "=r"(r[2]), "=r"(r[3]) : "r"(addr));
}
__device__ __forceinline__ void ldmx4t(uint32_t* r, uint32_t addr) {
    asm volatile("ldmatrix.sync.aligned.m8n8.x4.trans.shared.b16 {%0,%1,%2,%3}, [%4];"
        : "=r"(r[0]), "=r"(r[1]), "=r"(r[2]), "=r"(r[3]) : "r"(addr));
}
__device__ __forceinline__ uint32_t smem_u32(const void* p) {
    uint32_t a;
    asm("{ .reg .u64 t; cvta.to.shared.u64 t, %1; cvt.u32.u64 %0, t; }" : "=r"(a) : "l"(p));
    return a;
}
__device__ __forceinline__ uint32_t pack2h(float a, float b) {
    __half2 p = __floats2half2_rn(a, b);
    return *(uint32_t*)&p;
}
__device__ __forceinline__ void split4(float4 v, uint32_t& hA, uint32_t& hB,
                                       uint32_t& lA, uint32_t& lB) {
    f16 h0 = __float2half_rn(v.x), h1 = __float2half_rn(v.y);
    f16 h2 = __float2half_rn(v.z), h3 = __float2half_rn(v.w);
    __half2 a, b, c, d;
    a.x = h0; a.y = h1; b.x = h2; b.y = h3;
    c.x = __float2half_rn(v.x - __half2float(h0));
    c.y = __float2half_rn(v.y - __half2float(h1));
    d.x = __float2half_rn(v.z - __half2float(h2));
    d.y = __float2half_rn(v.w - __half2float(h3));
    hA = *(uint32_t*)&a; hB = *(uint32_t*)&b;
    lA = *(uint32_t*)&c; lB = *(uint32_t*)&d;
}

// ----------------------------------------------------------------------------
// Embedding + positional encoding
// ----------------------------------------------------------------------------
__global__ void embed_k(const int* __restrict__ x, const float* __restrict__ emb,
                        float* __restrict__ h) {
    int idx = blockIdx.x * blockDim.x + threadIdx.x;
    if (idx >= MM * DD) return;
    int row = idx >> 10, d = idx & 1023;
    int s = row % SS;
    int tok = x[row];
    int i2 = d & ~1;
    float div = expf(-(float)i2 * (logf(10000.0f) / (float)DD));
    float ang = (float)s * div;
    float pe = (d & 1) ? cosf(ang) : sinf(ang);
    h[idx] = emb[(size_t)tok * DD + d] + pe;
}

// ----------------------------------------------------------------------------
// LayerNorm (torch: ddof=1, eps on std)
// ----------------------------------------------------------------------------
__global__ __launch_bounds__(256) void layernorm_k(
    const float* __restrict__ x, const float* __restrict__ a,
    const float* __restrict__ b, float* __restrict__ out) {
    int row = blockIdx.x;
    const float* xp = x + (size_t)row * DD;
    int t4 = threadIdx.x * 4;
    float4 xv = *(const float4*)(xp + t4);
    float mean = blk_sum256(xv.x + xv.y + xv.z + xv.w) * (1.0f / DD);
    float d0 = xv.x - mean, d1 = xv.y - mean, d2 = xv.z - mean, d3 = xv.w - mean;
    float var = blk_sum256(d0*d0 + d1*d1 + d2*d2 + d3*d3) * (1.0f / (DD - 1));
    float inv = 1.0f / (sqrtf(var) + LN_EPS);
    float4 av = *(const float4*)(a + t4);
    float4 bv = *(const float4*)(b + t4);
    float4 r;
    r.x = av.x * d0 * inv + bv.x; r.y = av.y * d1 * inv + bv.y;
    r.z = av.z * d2 * inv + bv.z; r.w = av.w * d3 * inv + bv.w;
    *(float4*)(out + (size_t)row * DD + t4) = r;
}

// LayerNorm -> fp16 output
__global__ __launch_bounds__(256) void ln_h_k(
    const float* __restrict__ x, const float* __restrict__ a,
    const float* __restrict__ b, f16* __restrict__ y) {
    int row = blockIdx.x;
    const float* xp = x + (size_t)row * DD;
    int t4 = threadIdx.x * 4;
    float4 xv = *(const float4*)(xp + t4);
    float mean = blk_sum256(xv.x + xv.y + xv.z + xv.w) * (1.0f / DD);
    float d0 = xv.x - mean, d1 = xv.y - mean, d2 = xv.z - mean, d3 = xv.w - mean;
    float var = blk_sum256(d0*d0 + d1*d1 + d2*d2 + d3*d3) * (1.0f / (DD - 1));
    float inv = 1.0f / (sqrtf(var) + LN_EPS);
    float4 av = *(const float4*)(a + t4);
    float4 bv = *(const float4*)(b + t4);
    uint32_t* py = (uint32_t*)(y + (size_t)row * DD + t4);
    py[0] = pack2h(av.x * d0 * inv + bv.x, av.y * d1 * inv + bv.y);
    py[1] = pack2h(av.z * d2 * inv + bv.z, av.w * d3 * inv + bv.w);
}

// ----------------------------------------------------------------------------
// Weight transpose + fp16 conversion: W[K][N] -> T[N][K]
// ----------------------------------------------------------------------------
__global__ void convt_k(const float* __restrict__ W, f16* __restrict__ Th,
                        int K, int N) {
    __shared__ float t[32][33];
    int n0 = blockIdx.x * 32, k0 = blockIdx.y * 32;
    int tx = threadIdx.x, ty = threadIdx.y;
    #pragma unroll
    for (int i = ty; i < 32; i += 8) t[i][tx] = W[(size_t)(k0 + i) * N + n0 + tx];
    __syncthreads();
    #pragma unroll
    for (int i = ty; i < 32; i += 8)
        Th[(size_t)(n0 + i) * K + k0 + tx] = __float2half_rn(t[tx][i]);
}

// ----------------------------------------------------------------------------
// fp16 GEMM via mma.sync + ldmatrix:  C[M,N] = A[M,K] @ B^T[N,K]
// A fp16 activations, B fp16 weights. 128x128 CTA tile, BK=64,
// 2-stage cp.async, 8 warps of 32x64. Stage = A|B 16KB each = 32KB.
// MODE 0: Cf = acc+bias | MODE 1: Cf += acc+bias | MODE 2: relu -> fp16
// ----------------------------------------------------------------------------
#define SA_B 0
#define SB_B 16384
#define STAGE_B 32768
#define GEMM_SMEM (2*STAGE_B)

template<int MODE>
__global__ __launch_bounds__(256) void tgemm_k(
    const f16* __restrict__ A, const f16* __restrict__ Bw,
    const float* __restrict__ bias, float* __restrict__ Cf,
    f16* __restrict__ Of,
    int M, int N, int K) {
    extern __shared__ __align__(1024) char smem[];
    const uint32_t sb = smem_u32(smem);
    const int tid = threadIdx.x;
    const int lane = tid & 31, wid = tid >> 5;
    const int wm = wid >> 1, wn = wid & 1;
    const int bm = blockIdx.y * 128;
    const int bn = blockIdx.x * 128;
    const int lr = lane & 15, lh = lane >> 4;
    const int g = lane >> 2, tig = lane & 3;

    float acc[2][8][4];
    #pragma unroll
    for (int i = 0; i < 2; i++)
        #pragma unroll
        for (int j = 0; j < 8; j++)
            #pragma unroll
            for (int r = 0; r < 4; r++) acc[i][j][r] = 0.f;

    const int nc = K >> 6;

    #define PF(stg, kof)                                                          \
    {                                                                             \
        uint32_t base = sb + (stg) * STAGE_B;                                     \
        _Pragma("unroll")                                                         \
        for (int j = 0; j < 4; j++) {                                             \
            int idx = tid + 256 * j;                                              \
            int row = idx >> 3, u = idx & 7;                                      \
            uint32_t doff = (uint32_t)(row * 128) + (uint32_t)(((u ^ (row & 7)) << 4)); \
            int gr = bm + row;                                                    \
            int sz = (gr < M) ? 16 : 0;                                           \
            int grc = (gr < M) ? gr : 0;                                          \
            cp16(base + SA_B + doff, A + (size_t)grc * K + (kof) + u * 8, sz);    \
            int gn = bn + row;                                                    \
            cp16(base + SB_B + doff, Bw + (size_t)gn * K + (kof) + u * 8, 16);    \
        }                                                                         \
    }

    PF(0, 0);
    cp_commit();

    for (int i = 0; i < nc; i++) {
        if (i + 1 < nc) {
            PF((i + 1) & 1, (i + 1) * 64);
            cp_commit();
            cp_wait<1>();
        } else {
            cp_wait<0>();
        }
        __syncthreads();

        uint32_t base = sb + (i & 1) * STAGE_B;
        #pragma unroll
        for (int kq = 0; kq < 4; kq++) {
            uint32_t fa[2][4], fb[4][4];
            #pragma unroll
            for (int mt = 0; mt < 2; mt++) {
                int row = wm * 32 + mt * 16 + lr;
                uint32_t chunk = (uint32_t)(kq * 2 + lh);
                uint32_t off = (uint32_t)(row * 128) + (((chunk ^ (uint32_t)(row & 7)) << 4));
                ldmx4(fa[mt], base + SA_B + off);
            }
            #pragma unroll
            for (int j = 0; j < 4; j++) {
                int row = wn * 64 + j * 16 + lr;
                uint32_t chunk = (uint32_t)(kq * 2 + lh);
                uint32_t off = (uint32_t)(row * 128) + (((chunk ^ (uint32_t)(row & 7)) << 4));
                ldmx4(fb[j], base + SB_B + off);
            }
            #pragma unroll
            for (int mt = 0; mt < 2; mt++)
                #pragma unroll
                for (int nt = 0; nt < 8; nt++) {
                    int j = nt >> 1, sel = nt & 1;
                    uint32_t bb[2] = { fb[j][sel], fb[j][sel + 2] };
                    mma16816(acc[mt][nt], fa[mt], bb);
                }
        }
        __syncthreads();
    }

    #pragma unroll
    for (int mt = 0; mt < 2; mt++) {
        #pragma unroll
        for (int nt = 0; nt < 8; nt++) {
            int c = bn + wn * 64 + nt * 8 + tig * 2;
            float bx = bias[c], by = bias[c + 1];
            #pragma unroll
            for (int half = 0; half < 2; half++) {
                int r = bm + wm * 32 + mt * 16 + g + half * 8;
                if (r >= M) continue;
                float v0 = acc[mt][nt][half * 2 + 0] + bx;
                float v1 = acc[mt][nt][half * 2 + 1] + by;
                if (MODE == 1) {
                    float2 old = *(float2*)(Cf + (size_t)r * N + c);
                    v0 += old.x; v1 += old.y;
                    float2 o; o.x = v0; o.y = v1;
                    *(float2*)(Cf + (size_t)r * N + c) = o;
                } else if (MODE == 2) {
                    v0 = fmaxf(v0, 0.f); v1 = fmaxf(v1, 0.f);
                    *(uint32_t*)(Of + (size_t)r * N + c) = pack2h(v0, v1);
                } else {
                    float2 o; o.x = v0; o.y = v1;
                    *(float2*)(Cf + (size_t)r * N + c) = o;
                }
            }
        }
    }
    #undef PF
}

// ----------------------------------------------------------------------------
// Fused flash attention: per CTA one (b,h) x 64-q-row tile, 128 threads.
// Q,K fp16 hi/lo (3-term QK^T), online softmax fp32, P fp16, V fp16 hi/lo.
// ----------------------------------------------------------------------------
__global__ __launch_bounds__(128) void flash_k(
    const float* __restrict__ QKV, f16* __restrict__ O) {
    __shared__ __align__(1024) char sm[32768];
    const uint32_t sQV = smem_u32(sm);
    const uint32_t sK  = sQV + 16384;
    const int tid = threadIdx.x, lane = tid & 31, wid = tid >> 5;
    const int lr = lane & 15, lh = lane >> 4;
    const int g = lane >> 2, tig = lane & 3;
    const int bh = blockIdx.y, b = bh >> 4, h = bh & 15;
    const int q0 = blockIdx.x * 64;
    const float* Qg = QKV + (size_t)b * SS * QKVN + h * 64;
    const float* Kg = Qg + DD;
    const float* Vg = Qg + 2 * DD;

    #pragma unroll
    for (int j = 0; j < 8; j++) {
        int slot = tid + 128 * j;
        int row = slot >> 4, c4 = slot & 15;
        int qrow = q0 + row;
        float4 v = make_float4(0.f, 0.f, 0.f, 0.f);
        if (qrow < SS) v = *(const float4*)(Qg + (size_t)qrow * QKVN + c4 * 4);
        uint32_t hA, hB, lA, lB;
        split4(v, hA, hB, lA, lB);
        uint32_t off = (uint32_t)(row * 128) + ((((uint32_t)(c4 >> 1)) ^ (uint32_t)(row & 7)) << 4) + (c4 & 1) * 8;
        *(uint32_t*)(sm + off) = hA;          *(uint32_t*)(sm + off + 4) = hB;
        *(uint32_t*)(sm + 8192 + off) = lA;   *(uint32_t*)(sm + 8192 + off + 4) = lB;
    }
    __syncthreads();

    uint32_t qh[4][4], ql[4][4];
    #pragma unroll
    for (int kq = 0; kq < 4; kq++) {
        int row = wid * 16 + lr;
        uint32_t chunk = (uint32_t)(kq * 2 + lh);
        uint32_t off = (uint32_t)(row * 128) + ((chunk ^ (uint32_t)(row & 7)) << 4);
        ldmx4(qh[kq], sQV + off);
        ldmx4(ql[kq], sQV + 8192 + off);
    }

    float m0 = -1e30f, m1 = -1e30f, l0 = 0.f, l1 = 0.f;
    float ao[8][4];
    #pragma unroll
    for (int j = 0; j < 8; j++)
        #pragma unroll
        for (int r = 0; r < 4; r++) ao[j][r] = 0.f;

    for (int k0 = 0; k0 < SS; k0 += 64) {
        __syncthreads();
        #pragma unroll
        for (int j = 0; j < 8; j++) {
            int slot = tid + 128 * j;
            int row = slot >> 4, c4 = slot & 15;
            int krow = k0 + row;
            float4 kv = make_float4(0.f, 0.f, 0.f, 0.f);
            float4 vv = make_float4(0.f, 0.f, 0.f, 0.f);
            if (krow < SS) {
                kv = *(const float4*)(Kg + (size_t)krow * QKVN + c4 * 4);
                vv = *(const float4*)(Vg + (size_t)krow * QKVN + c4 * 4);
            }
            uint32_t off = (uint32_t)(row * 128) + ((((uint32_t)(c4 >> 1)) ^ (uint32_t)(row & 7)) << 4) + (c4 & 1) * 8;
            uint32_t hA, hB, lA, lB;
            split4(kv, hA, hB, lA, lB);
            *(uint32_t*)(sm + 16384 + off) = hA;  *(uint32_t*)(sm + 16384 + off + 4) = hB;
            *(uint32_t*)(sm + 24576 + off) = lA;  *(uint32_t*)(sm + 24576 + off + 4) = lB;
            split4(vv, hA, hB, lA, lB);
            *(uint32_t*)(sm + off) = hA;          *(uint32_t*)(sm + off + 4) = hB;
            *(uint32_t*)(sm + 8192 + off) = lA;   *(uint32_t*)(sm + 8192 + off + 4) = lB;
        }
        __syncthreads();

        float s[8][4];
        #pragma unroll
        for (int nt = 0; nt < 8; nt++)
            #pragma unroll
            for (int r = 0; r < 4; r++) s[nt][r] = 0.f;
        #pragma unroll
        for (int kq = 0; kq < 4; kq++) {
            uint32_t fkh[4][4], fkl[4][4];
            #pragma unroll
            for (int j2 = 0; j2 < 4; j2++) {
                int row = j2 * 16 + lr;
                uint32_t chunk = (uint32_t)(kq * 2 + lh);
                uint32_t off = (uint32_t)(row * 128) + ((chunk ^ (uint32_t)(row & 7)) << 4);
                ldmx4(fkh[j2], sK + off);
                ldmx4(fkl[j2], sK + 8192 + off);
            }
            #pragma unroll
            for (int nt = 0; nt < 8; nt++) {
                int j2 = nt >> 1, sel = nt & 1;
                uint32_t bhh[2] = { fkh[j2][sel], fkh[j2][sel + 2] };
                uint32_t bll[2] = { fkl[j2][sel], fkl[j2][sel + 2] };
                mma16816(s[nt], qh[kq], bhh);
                mma16816(s[nt], qh[kq], bll);
                mma16816(s[nt], ql[kq], bhh);
            }
        }
        bool tail = (k0 + 64 > SS);
        #pragma unroll
        for (int nt = 0; nt < 8; nt++)
            #pragma unroll
            for (int r = 0; r < 4; r++) {
                s[nt][r] *= 0.125f;
                if (tail && (k0 + nt * 8 + tig * 2 + (r & 1)) >= SS) s[nt][r] = -1e30f;
            }
        float mx0 = -1e30f, mx1 = -1e30f;
        #pragma unroll
        for (int nt = 0; nt < 8; nt++) {
            mx0 = fmaxf(mx0, fmaxf(s[nt][0], s[nt][1]));
            mx1 = fmaxf(mx1, fmaxf(s[nt][2], s[nt][3]));
        }
        mx0 = fmaxf(mx0, __shfl_xor_sync(0xffffffffu, mx0, 1));
        mx0 = fmaxf(mx0, __shfl_xor_sync(0xffffffffu, mx0, 2));
        mx1 = fmaxf(mx1, __shfl_xor_sync(0xffffffffu, mx1, 1));
        mx1 = fmaxf(mx1, __shfl_xor_sync(0xffffffffu, mx1, 2));
        float mn0 = fmaxf(m0, mx0), mn1 = fmaxf(m1, mx1);
        float sc0 = __expf(m0 - mn0), sc1 = __expf(m1 - mn1);
        m0 = mn0; m1 = mn1;
        float rs0 = 0.f, rs1 = 0.f;
        #pragma unroll
        for (int nt = 0; nt < 8; nt++) {
            s[nt][0] = __expf(s[nt][0] - m0); rs0 += s[nt][0];
            s[nt][1] = __expf(s[nt][1] - m0); rs0 += s[nt][1];
            s[nt][2] = __expf(s[nt][2] - m1); rs1 += s[nt][2];
            s[nt][3] = __expf(s[nt][3] - m1); rs1 += s[nt][3];
        }
        rs0 += __shfl_xor_sync(0xffffffffu, rs0, 1);
        rs0 += __shfl_xor_sync(0xffffffffu, rs0, 2);
        rs1 += __shfl_xor_sync(0xffffffffu, rs1, 1);
        rs1 += __shfl_xor_sync(0xffffffffu, rs1, 2);
        l0 = l0 * sc0 + rs0; l1 = l1 * sc1 + rs1;
        #pragma unroll
        for (int j = 0; j < 8; j++) {
            ao[j][0] *= sc0; ao[j][1] *= sc0;
            ao[j][2] *= sc1; ao[j][3] *= sc1;
        }
        #pragma unroll
        for (int kc = 0; kc < 4; kc++) {
            uint32_t pa[4] = {
                pack2h(s[2*kc][0],   s[2*kc][1]),
                pack2h(s[2*kc][2],   s[2*kc][3]),
                pack2h(s[2*kc+1][0], s[2*kc+1][1]),
                pack2h(s[2*kc+1][2], s[2*kc+1][3]) };
            int vrow = kc * 16 + (lane & 7) + ((lane & 8) ? 8 : 0);
            #pragma unroll
            for (int dp = 0; dp < 4; dp++) {
                uint32_t u = (uint32_t)(dp * 2 + ((lane & 16) ? 1 : 0));
                uint32_t off = (uint32_t)(vrow * 128) + ((u ^ (uint32_t)(vrow & 7)) << 4);
                uint32_t fvh[4], fvl[4];
                ldmx4t(fvh, sQV + off);
                ldmx4t(fvl, sQV + 8192 + off);
                uint32_t b0h[2] = { fvh[0], fvh[1] }, b1h[2] = { fvh[2], fvh[3] };
                uint32_t b0l[2] = { fvl[0], fvl[1] }, b1l[2] = { fvl[2], fvl[3] };
                mma16816(ao[dp*2],     pa, b0h);
                mma16816(ao[dp*2],     pa, b0l);
                mma16816(ao[dp*2 + 1], pa, b1h);
                mma16816(ao[dp*2 + 1], pa, b1l);
            }
        }
    }

    float il0 = 1.f / l0, il1 = 1.f / l1;
    int r0 = q0 + wid * 16 + g, r1 = r0 + 8;
    #pragma unroll
    for (int j = 0; j < 8; j++) {
        int d = h * 64 + j * 8 + tig * 2;
        if (r0 < SS)
            *(uint32_t*)(O + (size_t)(b * SS + r0) * DD + d) = pack2h(ao[j][0] * il0, ao[j][1] * il0);
        if (r1 < SS)
            *(uint32_t*)(O + (size_t)(b * SS + r1) * DD + d) = pack2h(ao[j][2] * il1, ao[j][3] * il1);
    }
}

// ----------------------------------------------------------------------------
// Host orchestration
// ----------------------------------------------------------------------------
extern "C" void kernel_launch(void* const* d_in, const int* in_sizes, int n_in,
                              void* d_out, int out_size) {
    const int*   x      = (const int*)d_in[0];
    const float* emb    = (const float*)d_in[1];
    const float* attn_w = (const float*)d_in[2];
    const float* attn_b = (const float*)d_in[3];
    const float* ln_a   = (const float*)d_in[4];
    const float* ln_b   = (const float*)d_in[5];
    const float* w1     = (const float*)d_in[6];
    const float* b1     = (const float*)d_in[7];
    const float* w2     = (const float*)d_in[8];
    const float* b2     = (const float*)d_in[9];
    const float* na     = (const float*)d_in[10];
    const float* nb     = (const float*)d_in[11];
    float* out = (float*)d_out;

    float *h, *qkv;
    f16 *y, *o, *f;
    f16 *wq, *wo, *wf1, *wf2;
    cudaGetSymbolAddress((void**)&h, g_h);
    cudaGetSymbolAddress((void**)&qkv, g_qkv);
    cudaGetSymbolAddress((void**)&y, g_y);
    cudaGetSymbolAddress((void**)&o, g_o);
    cudaGetSymbolAddress((void**)&f, g_f);
    cudaGetSymbolAddress((void**)&wq, g_wqkv);
    cudaGetSymbolAddress((void**)&wo, g_wo);
    cudaGetSymbolAddress((void**)&wf1, g_w1);
    cudaGetSymbolAddress((void**)&wf2, g_w2);

    cudaFuncSetAttribute(tgemm_k<0>, cudaFuncAttributeMaxDynamicSharedMemorySize, GEMM_SMEM);
    cudaFuncSetAttribute(tgemm_k<1>, cudaFuncAttributeMaxDynamicSharedMemorySize, GEMM_SMEM);
    cudaFuncSetAttribute(tgemm_k<2>, cudaFuncAttributeMaxDynamicSharedMemorySize, GEMM_SMEM);

    // weight transpose-convert
    dim3 cb(32, 8);
    for (int l = 0; l < LL; l++) {
        for (int t = 0; t < 3; t++)
            convt_k<<<dim3(DD/32, DD/32), cb>>>(
                attn_w + ((size_t)(l*4 + t))*DD*DD,
                wq + ((size_t)(l*3 + t))*DD*DD, DD, DD);
        convt_k<<<dim3(DD/32, DD/32), cb>>>(
            attn_w + ((size_t)(l*4 + 3))*DD*DD,
            wo + (size_t)l*DD*DD, DD, DD);
        convt_k<<<dim3(FF/32, DD/32), cb>>>(
            w1 + (size_t)l*DD*FF, wf1 + (size_t)l*FF*DD, DD, FF);
        convt_k<<<dim3(DD/32, FF/32), cb>>>(
            w2 + (size_t)l*FF*DD, wf2 + (size_t)l*DD*FF, FF, DD);
    }

    embed_k<<<(MM * DD + 255) / 256, 256>>>(x, emb, h);

    dim3 gQKV(QKVN / 128, (MM + 127) / 128);   // (24, 32)
    dim3 gD(DD / 128, (MM + 127) / 128);       // (8, 32)
    dim3 gF(FF / 128, (MM + 127) / 128);       // (32, 32)
    dim3 gFA(8, BB * HH);

    for (int l = 0; l < LL; l++) {
        const float* Wb = attn_b + (size_t)l * 4 * DD;
        const float* la = ln_a + (size_t)l * 2 * DD;
        const float* lb = ln_b + (size_t)l * 2 * DD;

        // attention sublayer
        ln_h_k<<<MM, 256>>>(h, la, lb, y);
        tgemm_k<0><<<gQKV, 256, GEMM_SMEM>>>(y,
            wq + (size_t)l*QKVN*DD, Wb, qkv, nullptr, MM, QKVN, DD);
        flash_k<<<gFA, 128>>>(qkv, o);
        tgemm_k<1><<<gD, 256, GEMM_SMEM>>>(o,
            wo + (size_t)l*DD*DD, Wb + 3*DD, h, nullptr, MM, DD, DD);

        // feed-forward sublayer
        ln_h_k<<<MM, 256>>>(h, la + DD, lb + DD, y);
        tgemm_k<2><<<gF, 256, GEMM_SMEM>>>(y,
            wf1 + (size_t)l*FF*DD, b1 + (size_t)l*FF, nullptr, f, MM, FF, DD);
        tgemm_k<1><<<gD, 256, GEMM_SMEM>>>(f,
            wf2 + (size_t)l*DD*FF, b2 + (size_t)l*DD, h, nullptr, MM, DD, FF);
    }

    layernorm_k<<<MM, 256>>>(h, na, nb, out);
}

// round 11
// speedup vs baseline: 6.6929x; 1.0211x over previous
#include <cuda_runtime.h>
#include <cuda_bf16.h>
#include <cuda_fp16.h>
#include <math.h>
#include <stdint.h>

#define BB 8
#define SS 500
#define DD 1024
#define HH 16
#define LL 4
#define FF 4096
#define MM (BB*SS)          // 4000
#define QKVN (3*DD)         // 3072
#define LN_EPS 1e-6f

typedef __half f16;

// ----------------------------------------------------------------------------
// Scratch (device globals; allocation-free)
// ----------------------------------------------------------------------------
__device__ __align__(128) float g_h[(size_t)MM*DD];
__device__ __align__(128) float g_qkv[(size_t)MM*QKVN];
__device__ __align__(128) f16 g_y[(size_t)MM*DD];
__device__ __align__(128) f16 g_o[(size_t)MM*DD];
__device__ __align__(128) f16 g_f[(size_t)MM*FF];
// transposed weights, fp16, layout [N][K]
__device__ __align__(128) f16 g_wqkv[(size_t)LL*QKVN*DD];
__device__ __align__(128) f16 g_wo[(size_t)LL*DD*DD];
__device__ __align__(128) f16 g_w1[(size_t)LL*FF*DD];
__device__ __align__(128) f16 g_w2[(size_t)LL*DD*FF];

// ----------------------------------------------------------------------------
// Helpers
// ----------------------------------------------------------------------------
__device__ __forceinline__ float blk_sum256(float v) {
    __shared__ float sh[8];
    #pragma unroll
    for (int o = 16; o > 0; o >>= 1) v += __shfl_down_sync(0xffffffffu, v, o);
    __syncthreads();
    if ((threadIdx.x & 31) == 0) sh[threadIdx.x >> 5] = v;
    __syncthreads();
    float t = 0.f;
    #pragma unroll
    for (int i = 0; i < 8; i++) t += sh[i];
    return t;
}

__device__ __forceinline__ void cp16(uint32_t dst, const void* src, int sz) {
    asm volatile("cp.async.cg.shared.global [%0], [%1], 16, %2;\n"
                 :: "r"(dst), "l"(src), "r"(sz));
}
__device__ __forceinline__ void cp_commit() { asm volatile("cp.async.commit_group;\n"); }
template<int N> __device__ __forceinline__ void cp_wait() {
    asm volatile("cp.async.wait_group %0;\n" :: "n"(N));
}
__device__ __forceinline__ void mma16816(float* c, const uint32_t* a, const uint32_t* b) {
    asm volatile("mma.sync.aligned.m16n8k16.row.col.f32.f16.f16.f32 "
        "{%0,%1,%2,%3},{%4,%5,%6,%7},{%8,%9},{%0,%1,%2,%3};\n"
        : "+f"(c[0]), "+f"(c[1]), "+f"(c[2]), "+f"(c[3])
        : "r"(a[0]), "r"(a[1]), "r"(a[2]), "r"(a[3]), "r"(b[0]), "r"(b[1]));
}
__device__ __forceinline__ void ldmx4(uint32_t* r, uint32_t addr) {
    asm volatile("ldmatrix.sync.aligned.m8n8.x4.shared.b16 {%0,%1,%2,%3}, [%4];"
        : "=r"(r[0]), "=r"(r[1]), "=r"(r[2]), "=r"(r[3]) : "r"(addr));
}
__device__ __forceinline__ void ldmx4t(uint32_t* r, uint32_t addr) {
    asm volatile("ldmatrix.sync.aligned.m8n8.x4.trans.shared.b16 {%0,%1,%2,%3}, [%4];"
        : "=r"(r[0]), "=r"(r[1]), "=r"(r[2]), "=r"(r[3]) : "r"(addr));
}
__device__ __forceinline__ uint32_t smem_u32(const void* p) {
    uint32_t a;
    asm("{ .reg .u64 t; cvta.to.shared.u64 t, %1; cvt.u32.u64 %0, t; }" : "=r"(a) : "l"(p));
    return a;
}
__device__ __forceinline__ uint32_t pack2h(float a, float b) {
    __half2 p = __floats2half2_rn(a, b);
    return *(uint32_t*)&p;
}
__device__ __forceinline__ void split4(float4 v, uint32_t& hA, uint32_t& hB,
                                       uint32_t& lA, uint32_t& lB) {
    f16 h0 = __float2half_rn(v.x), h1 = __float2half_rn(v.y);
    f16 h2 = __float2half_rn(v.z), h3 = __float2half_rn(v.w);
    __half2 a, b, c, d;
    a.x = h0; a.y = h1; b.x = h2; b.y = h3;
    c.x = __float2half_rn(v.x - __half2float(h0));
    c.y = __float2half_rn(v.y - __half2float(h1));
    d.x = __float2half_rn(v.z - __half2float(h2));
    d.y = __float2half_rn(v.w - __half2float(h3));
    hA = *(uint32_t*)&a; hB = *(uint32_t*)&b;
    lA = *(uint32_t*)&c; lB = *(uint32_t*)&d;
}

// ----------------------------------------------------------------------------
// Embedding + positional encoding
// ----------------------------------------------------------------------------
__global__ void embed_k(const int* __restrict__ x, const float* __restrict__ emb,
                        float* __restrict__ h) {
    int idx = blockIdx.x * blockDim.x + threadIdx.x;
    if (idx >= MM * DD) return;
    int row = idx >> 10, d = idx & 1023;
    int s = row % SS;
    int tok = x[row];
    int i2 = d & ~1;
    float div = expf(-(float)i2 * (logf(10000.0f) / (float)DD));
    float ang = (float)s * div;
    float pe = (d & 1) ? cosf(ang) : sinf(ang);
    h[idx] = emb[(size_t)tok * DD + d] + pe;
}

// ----------------------------------------------------------------------------
// LayerNorm (torch: ddof=1, eps on std)
// ----------------------------------------------------------------------------
__global__ __launch_bounds__(256) void layernorm_k(
    const float* __restrict__ x, const float* __restrict__ a,
    const float* __restrict__ b, float* __restrict__ out) {
    int row = blockIdx.x;
    const float* xp = x + (size_t)row * DD;
    int t4 = threadIdx.x * 4;
    float4 xv = *(const float4*)(xp + t4);
    float mean = blk_sum256(xv.x + xv.y + xv.z + xv.w) * (1.0f / DD);
    float d0 = xv.x - mean, d1 = xv.y - mean, d2 = xv.z - mean, d3 = xv.w - mean;
    float var = blk_sum256(d0*d0 + d1*d1 + d2*d2 + d3*d3) * (1.0f / (DD - 1));
    float inv = 1.0f / (sqrtf(var) + LN_EPS);
    float4 av = *(const float4*)(a + t4);
    float4 bv = *(const float4*)(b + t4);
    float4 r;
    r.x = av.x * d0 * inv + bv.x; r.y = av.y * d1 * inv + bv.y;
    r.z = av.z * d2 * inv + bv.z; r.w = av.w * d3 * inv + bv.w;
    *(float4*)(out + (size_t)row * DD + t4) = r;
}

// LayerNorm -> fp16 output
__global__ __launch_bounds__(256) void ln_h_k(
    const float* __restrict__ x, const float* __restrict__ a,
    const float* __restrict__ b, f16* __restrict__ y) {
    int row = blockIdx.x;
    const float* xp = x + (size_t)row * DD;
    int t4 = threadIdx.x * 4;
    float4 xv = *(const float4*)(xp + t4);
    float mean = blk_sum256(xv.x + xv.y + xv.z + xv.w) * (1.0f / DD);
    float d0 = xv.x - mean, d1 = xv.y - mean, d2 = xv.z - mean, d3 = xv.w - mean;
    float var = blk_sum256(d0*d0 + d1*d1 + d2*d2 + d3*d3) * (1.0f / (DD - 1));
    float inv = 1.0f / (sqrtf(var) + LN_EPS);
    float4 av = *(const float4*)(a + t4);
    float4 bv = *(const float4*)(b + t4);
    uint32_t* py = (uint32_t*)(y + (size_t)row * DD + t4);
    py[0] = pack2h(av.x * d0 * inv + bv.x, av.y * d1 * inv + bv.y);
    py[1] = pack2h(av.z * d2 * inv + bv.z, av.w * d3 * inv + bv.w);
}

// ----------------------------------------------------------------------------
// Merged weight transpose+fp16 convert: ALL matrices, ONE launch.
// Per layer tiles: qkv 3*1024, wo 1024, w1 4096, w2 4096 = 12288.
// ----------------------------------------------------------------------------
#define TILES_PER_LAYER 12288
__global__ void convt_all_k(
    const float* __restrict__ attn_w, const float* __restrict__ w1,
    const float* __restrict__ w2, f16* __restrict__ wq, f16* __restrict__ wo,
    f16* __restrict__ wf1, f16* __restrict__ wf2) {
    __shared__ float t[32][33];
    int id = blockIdx.x;
    int l = id / TILES_PER_LAYER, r = id % TILES_PER_LAYER;
    const float* W; f16* T; int K, N, tt;
    if (r < 3072) {
        int m = r >> 10; tt = r & 1023;
        W = attn_w + ((size_t)(l * 4 + m)) * DD * DD;
        T = wq + ((size_t)(l * 3 + m)) * DD * DD;
        K = DD; N = DD;
    } else if (r < 4096) {
        tt = r - 3072;
        W = attn_w + ((size_t)(l * 4 + 3)) * DD * DD;
        T = wo + (size_t)l * DD * DD;
        K = DD; N = DD;
    } else if (r < 8192) {
        tt = r - 4096;
        W = w1 + (size_t)l * DD * FF;
        T = wf1 + (size_t)l * FF * DD;
        K = DD; N = FF;
    } else {
        tt = r - 8192;
        W = w2 + (size_t)l * FF * DD;
        T = wf2 + (size_t)l * DD * FF;
        K = FF; N = DD;
    }
    int ntx = N >> 5;
    int n0 = (tt % ntx) * 32, k0 = (tt / ntx) * 32;
    int tx = threadIdx.x, ty = threadIdx.y;
    #pragma unroll
    for (int i = ty; i < 32; i += 8) t[i][tx] = W[(size_t)(k0 + i) * N + n0 + tx];
    __syncthreads();
    #pragma unroll
    for (int i = ty; i < 32; i += 8)
        T[(size_t)(n0 + i) * K + k0 + tx] = __float2half_rn(t[tx][i]);
}

// ----------------------------------------------------------------------------
// fp16 GEMM via mma.sync + ldmatrix:  C[M,N] = A[M,K] @ B^T[N,K]
// 128x128 CTA tile, BK=64, 3-stage cp.async (one sync per chunk),
// 8 warps of 32x64. Stage = A|B 16KB each = 32KB; 3 stages = 96KB.
// MODE 0: Cf = acc+bias | MODE 1: Cf += acc+bias | MODE 2: relu -> fp16
// ----------------------------------------------------------------------------
#define SA_B 0
#define SB_B 16384
#define STAGE_B 32768
#define GEMM_SMEM (3*STAGE_B)

template<int MODE>
__global__ __launch_bounds__(256) void tgemm_k(
    const f16* __restrict__ A, const f16* __restrict__ Bw,
    const float* __restrict__ bias, float* __restrict__ Cf,
    f16* __restrict__ Of,
    int M, int N, int K) {
    extern __shared__ __align__(1024) char smem[];
    const uint32_t sb = smem_u32(smem);
    const int tid = threadIdx.x;
    const int lane = tid & 31, wid = tid >> 5;
    const int wm = wid >> 1, wn = wid & 1;
    const int bm = blockIdx.y * 128;
    const int bn = blockIdx.x * 128;
    const int lr = lane & 15, lh = lane >> 4;
    const int g = lane >> 2, tig = lane & 3;

    float acc[2][8][4];
    #pragma unroll
    for (int i = 0; i < 2; i++)
        #pragma unroll
        for (int j = 0; j < 8; j++)
            #pragma unroll
            for (int r = 0; r < 4; r++) acc[i][j][r] = 0.f;

    const int nc = K >> 6;

    #define PF(stg, kof)                                                          \
    {                                                                             \
        uint32_t base = sb + (stg) * STAGE_B;                                     \
        _Pragma("unroll")                                                         \
        for (int j = 0; j < 4; j++) {                                             \
            int idx = tid + 256 * j;                                              \
            int row = idx >> 3, u = idx & 7;                                      \
            uint32_t doff = (uint32_t)(row * 128) + (uint32_t)(((u ^ (row & 7)) << 4)); \
            int gr = bm + row;                                                    \
            int sz = (gr < M) ? 16 : 0;                                           \
            int grc = (gr < M) ? gr : 0;                                          \
            cp16(base + SA_B + doff, A + (size_t)grc * K + (kof) + u * 8, sz);    \
            int gn = bn + row;                                                    \
            cp16(base + SB_B + doff, Bw + (size_t)gn * K + (kof) + u * 8, 16);    \
        }                                                                         \
    }

    PF(0, 0);
    cp_commit();
    if (nc > 1) { PF(1, 64); }
    cp_commit();

    int stg = 0;
    for (int i = 0; i < nc; i++) {
        cp_wait<1>();
        __syncthreads();
        if (i + 2 < nc) {
            int ns = (stg + 2) % 3;
            PF(ns, (i + 2) * 64);
        }
        cp_commit();

        uint32_t base = sb + stg * STAGE_B;
        #pragma unroll
        for (int kq = 0; kq < 4; kq++) {
            uint32_t fa[2][4], fb[4][4];
            #pragma unroll
            for (int mt = 0; mt < 2; mt++) {
                int row = wm * 32 + mt * 16 + lr;
                uint32_t chunk = (uint32_t)(kq * 2 + lh);
                uint32_t off = (uint32_t)(row * 128) + (((chunk ^ (uint32_t)(row & 7)) << 4));
                ldmx4(fa[mt], base + SA_B + off);
            }
            #pragma unroll
            for (int j = 0; j < 4; j++) {
                int row = wn * 64 + j * 16 + lr;
                uint32_t chunk = (uint32_t)(kq * 2 + lh);
                uint32_t off = (uint32_t)(row * 128) + (((chunk ^ (uint32_t)(row & 7)) << 4));
                ldmx4(fb[j], base + SB_B + off);
            }
            #pragma unroll
            for (int mt = 0; mt < 2; mt++)
                #pragma unroll
                for (int nt = 0; nt < 8; nt++) {
                    int j = nt >> 1, sel = nt & 1;
                    uint32_t bb[2] = { fb[j][sel], fb[j][sel + 2] };
                    mma16816(acc[mt][nt], fa[mt], bb);
                }
        }
        stg = (stg + 1) % 3;
    }

    #pragma unroll
    for (int mt = 0; mt < 2; mt++) {
        #pragma unroll
        for (int nt = 0; nt < 8; nt++) {
            int c = bn + wn * 64 + nt * 8 + tig * 2;
            float bx = bias[c], by = bias[c + 1];
            #pragma unroll
            for (int half = 0; half < 2; half++) {
                int r = bm + wm * 32 + mt * 16 + g + half * 8;
                if (r >= M) continue;
                float v0 = acc[mt][nt][half * 2 + 0] + bx;
                float v1 = acc[mt][nt][half * 2 + 1] + by;
                if (MODE == 1) {
                    float2 old = *(float2*)(Cf + (size_t)r * N + c);
                    v0 += old.x; v1 += old.y;
                    float2 o; o.x = v0; o.y = v1;
                    *(float2*)(Cf + (size_t)r * N + c) = o;
                } else if (MODE == 2) {
                    v0 = fmaxf(v0, 0.f); v1 = fmaxf(v1, 0.f);
                    *(uint32_t*)(Of + (size_t)r * N + c) = pack2h(v0, v1);
                } else {
                    float2 o; o.x = v0; o.y = v1;
                    *(float2*)(Cf + (size_t)r * N + c) = o;
                }
            }
        }
    }
    #undef PF
}

// ----------------------------------------------------------------------------
// Fused flash attention (unchanged from R9/R10)
// ----------------------------------------------------------------------------
__global__ __launch_bounds__(128) void flash_k(
    const float* __restrict__ QKV, f16* __restrict__ O) {
    __shared__ __align__(1024) char sm[32768];
    const uint32_t sQV = smem_u32(sm);
    const uint32_t sK  = sQV + 16384;
    const int tid = threadIdx.x, lane = tid & 31, wid = tid >> 5;
    const int lr = lane & 15, lh = lane >> 4;
    const int g = lane >> 2, tig = lane & 3;
    const int bh = blockIdx.y, b = bh >> 4, h = bh & 15;
    const int q0 = blockIdx.x * 64;
    const float* Qg = QKV + (size_t)b * SS * QKVN + h * 64;
    const float* Kg = Qg + DD;
    const float* Vg = Qg + 2 * DD;

    #pragma unroll
    for (int j = 0; j < 8; j++) {
        int slot = tid + 128 * j;
        int row = slot >> 4, c4 = slot & 15;
        int qrow = q0 + row;
        float4 v = make_float4(0.f, 0.f, 0.f, 0.f);
        if (qrow < SS) v = *(const float4*)(Qg + (size_t)qrow * QKVN + c4 * 4);
        uint32_t hA, hB, lA, lB;
        split4(v, hA, hB, lA, lB);
        uint32_t off = (uint32_t)(row * 128) + ((((uint32_t)(c4 >> 1)) ^ (uint32_t)(row & 7)) << 4) + (c4 & 1) * 8;
        *(uint32_t*)(sm + off) = hA;          *(uint32_t*)(sm + off + 4) = hB;
        *(uint32_t*)(sm + 8192 + off) = lA;   *(uint32_t*)(sm + 8192 + off + 4) = lB;
    }
    __syncthreads();

    uint32_t qh[4][4], ql[4][4];
    #pragma unroll
    for (int kq = 0; kq < 4; kq++) {
        int row = wid * 16 + lr;
        uint32_t chunk = (uint32_t)(kq * 2 + lh);
        uint32_t off = (uint32_t)(row * 128) + ((chunk ^ (uint32_t)(row & 7)) << 4);
        ldmx4(qh[kq], sQV + off);
        ldmx4(ql[kq], sQV + 8192 + off);
    }

    float m0 = -1e30f, m1 = -1e30f, l0 = 0.f, l1 = 0.f;
    float ao[8][4];
    #pragma unroll
    for (int j = 0; j < 8; j++)
        #pragma unroll
        for (int r = 0; r < 4; r++) ao[j][r] = 0.f;

    for (int k0 = 0; k0 < SS; k0 += 64) {
        __syncthreads();
        #pragma unroll
        for (int j = 0; j < 8; j++) {
            int slot = tid + 128 * j;
            int row = slot >> 4, c4 = slot & 15;
            int krow = k0 + row;
            float4 kv = make_float4(0.f, 0.f, 0.f, 0.f);
            float4 vv = make_float4(0.f, 0.f, 0.f, 0.f);
            if (krow < SS) {
                kv = *(const float4*)(Kg + (size_t)krow * QKVN + c4 * 4);
                vv = *(const float4*)(Vg + (size_t)krow * QKVN + c4 * 4);
            }
            uint32_t off = (uint32_t)(row * 128) + ((((uint32_t)(c4 >> 1)) ^ (uint32_t)(row & 7)) << 4) + (c4 & 1) * 8;
            uint32_t hA, hB, lA, lB;
            split4(kv, hA, hB, lA, lB);
            *(uint32_t*)(sm + 16384 + off) = hA;  *(uint32_t*)(sm + 16384 + off + 4) = hB;
            *(uint32_t*)(sm + 24576 + off) = lA;  *(uint32_t*)(sm + 24576 + off + 4) = lB;
            split4(vv, hA, hB, lA, lB);
            *(uint32_t*)(sm + off) = hA;          *(uint32_t*)(sm + off + 4) = hB;
            *(uint32_t*)(sm + 8192 + off) = lA;   *(uint32_t*)(sm + 8192 + off + 4) = lB;
        }
        __syncthreads();

        float s[8][4];
        #pragma unroll
        for (int nt = 0; nt < 8; nt++)
            #pragma unroll
            for (int r = 0; r < 4; r++) s[nt][r] = 0.f;
        #pragma unroll
        for (int kq = 0; kq < 4; kq++) {
            uint32_t fkh[4][4], fkl[4][4];
            #pragma unroll
            for (int j2 = 0; j2 < 4; j2++) {
                int row = j2 * 16 + lr;
                uint32_t chunk = (uint32_t)(kq * 2 + lh);
                uint32_t off = (uint32_t)(row * 128) + ((chunk ^ (uint32_t)(row & 7)) << 4);
                ldmx4(fkh[j2], sK + off);
                ldmx4(fkl[j2], sK + 8192 + off);
            }
            #pragma unroll
            for (int nt = 0; nt < 8; nt++) {
                int j2 = nt >> 1, sel = nt & 1;
                uint32_t bhh[2] = { fkh[j2][sel], fkh[j2][sel + 2] };
                uint32_t bll[2] = { fkl[j2][sel], fkl[j2][sel + 2] };
                mma16816(s[nt], qh[kq], bhh);
                mma16816(s[nt], qh[kq], bll);
                mma16816(s[nt], ql[kq], bhh);
            }
        }
        bool tail = (k0 + 64 > SS);
        #pragma unroll
        for (int nt = 0; nt < 8; nt++)
            #pragma unroll
            for (int r = 0; r < 4; r++) {
                s[nt][r] *= 0.125f;
                if (tail && (k0 + nt * 8 + tig * 2 + (r & 1)) >= SS) s[nt][r] = -1e30f;
            }
        float mx0 = -1e30f, mx1 = -1e30f;
        #pragma unroll
        for (int nt = 0; nt < 8; nt++) {
            mx0 = fmaxf(mx0, fmaxf(s[nt][0], s[nt][1]));
            mx1 = fmaxf(mx1, fmaxf(s[nt][2], s[nt][3]));
        }
        mx0 = fmaxf(mx0, __shfl_xor_sync(0xffffffffu, mx0, 1));
        mx0 = fmaxf(mx0, __shfl_xor_sync(0xffffffffu, mx0, 2));
        mx1 = fmaxf(mx1, __shfl_xor_sync(0xffffffffu, mx1, 1));
        mx1 = fmaxf(mx1, __shfl_xor_sync(0xffffffffu, mx1, 2));
        float mn0 = fmaxf(m0, mx0), mn1 = fmaxf(m1, mx1);
        float sc0 = __expf(m0 - mn0), sc1 = __expf(m1 - mn1);
        m0 = mn0; m1 = mn1;
        float rs0 = 0.f, rs1 = 0.f;
        #pragma unroll
        for (int nt = 0; nt < 8; nt++) {
            s[nt][0] = __expf(s[nt][0] - m0); rs0 += s[nt][0];
            s[nt][1] = __expf(s[nt][1] - m0); rs0 += s[nt][1];
            s[nt][2] = __expf(s[nt][2] - m1); rs1 += s[nt][2];
            s[nt][3] = __expf(s[nt][3] - m1); rs1 += s[nt][3];
        }
        rs0 += __shfl_xor_sync(0xffffffffu, rs0, 1);
        rs0 += __shfl_xor_sync(0xffffffffu, rs0, 2);
        rs1 += __shfl_xor_sync(0xffffffffu, rs1, 1);
        rs1 += __shfl_xor_sync(0xffffffffu, rs1, 2);
        l0 = l0 * sc0 + rs0; l1 = l1 * sc1 + rs1;
        #pragma unroll
        for (int j = 0; j < 8; j++) {
            ao[j][0] *= sc0; ao[j][1] *= sc0;
            ao[j][2] *= sc1; ao[j][3] *= sc1;
        }
        #pragma unroll
        for (int kc = 0; kc < 4; kc++) {
            uint32_t pa[4] = {
                pack2h(s[2*kc][0],   s[2*kc][1]),
                pack2h(s[2*kc][2],   s[2*kc][3]),
                pack2h(s[2*kc+1][0], s[2*kc+1][1]),
                pack2h(s[2*kc+1][2], s[2*kc+1][3]) };
            int vrow = kc * 16 + (lane & 7) + ((lane & 8) ? 8 : 0);
            #pragma unroll
            for (int dp = 0; dp < 4; dp++) {
                uint32_t u = (uint32_t)(dp * 2 + ((lane & 16) ? 1 : 0));
                uint32_t off = (uint32_t)(vrow * 128) + ((u ^ (uint32_t)(vrow & 7)) << 4);
                uint32_t fvh[4], fvl[4];
                ldmx4t(fvh, sQV + off);
                ldmx4t(fvl, sQV + 8192 + off);
                uint32_t b0h[2] = { fvh[0], fvh[1] }, b1h[2] = { fvh[2], fvh[3] };
                uint32_t b0l[2] = { fvl[0], fvl[1] }, b1l[2] = { fvl[2], fvl[3] };
                mma16816(ao[dp*2],     pa, b0h);
                mma16816(ao[dp*2],     pa, b0l);
                mma16816(ao[dp*2 + 1], pa, b1h);
                mma16816(ao[dp*2 + 1], pa, b1l);
            }
        }
    }

    float il0 = 1.f / l0, il1 = 1.f / l1;
    int r0 = q0 + wid * 16 + g, r1 = r0 + 8;
    #pragma unroll
    for (int j = 0; j < 8; j++) {
        int d = h * 64 + j * 8 + tig * 2;
        if (r0 < SS)
            *(uint32_t*)(O + (size_t)(b * SS + r0) * DD + d) = pack2h(ao[j][0] * il0, ao[j][1] * il0);
        if (r1 < SS)
            *(uint32_t*)(O + (size_t)(b * SS + r1) * DD + d) = pack2h(ao[j][2] * il1, ao[j][3] * il1);
    }
}

// ----------------------------------------------------------------------------
// Host orchestration
// ----------------------------------------------------------------------------
extern "C" void kernel_launch(void* const* d_in, const int* in_sizes, int n_in,
                              void* d_out, int out_size) {
    const int*   x      = (const int*)d_in[0];
    const float* emb    = (const float*)d_in[1];
    const float* attn_w = (const float*)d_in[2];
    const float* attn_b = (const float*)d_in[3];
    const float* ln_a   = (const float*)d_in[4];
    const float* ln_b   = (const float*)d_in[5];
    const float* w1     = (const float*)d_in[6];
    const float* b1     = (const float*)d_in[7];
    const float* w2     = (const float*)d_in[8];
    const float* b2     = (const float*)d_in[9];
    const float* na     = (const float*)d_in[10];
    const float* nb     = (const float*)d_in[11];
    float* out = (float*)d_out;

    float *h, *qkv;
    f16 *y, *o, *f;
    f16 *wq, *wo, *wf1, *wf2;
    cudaGetSymbolAddress((void**)&h, g_h);
    cudaGetSymbolAddress((void**)&qkv, g_qkv);
    cudaGetSymbolAddress((void**)&y, g_y);
    cudaGetSymbolAddress((void**)&o, g_o);
    cudaGetSymbolAddress((void**)&f, g_f);
    cudaGetSymbolAddress((void**)&wq, g_wqkv);
    cudaGetSymbolAddress((void**)&wo, g_wo);
    cudaGetSymbolAddress((void**)&wf1, g_w1);
    cudaGetSymbolAddress((void**)&wf2, g_w2);

    cudaFuncSetAttribute(tgemm_k<0>, cudaFuncAttributeMaxDynamicSharedMemorySize, GEMM_SMEM);
    cudaFuncSetAttribute(tgemm_k<1>, cudaFuncAttributeMaxDynamicSharedMemorySize, GEMM_SMEM);
    cudaFuncSetAttribute(tgemm_k<2>, cudaFuncAttributeMaxDynamicSharedMemorySize, GEMM_SMEM);

    // 1: merged weight transpose-convert (single launch)
    dim3 cb(32, 8);
    convt_all_k<<<LL * TILES_PER_LAYER, cb>>>(attn_w, w1, w2, wq, wo, wf1, wf2);

    // 2: embedding
    embed_k<<<(MM * DD + 255) / 256, 256>>>(x, emb, h);

    dim3 gQKV(QKVN / 128, (MM + 127) / 128);   // (24, 32)
    dim3 gD(DD / 128, (MM + 127) / 128);       // (8, 32)
    dim3 gF(FF / 128, (MM + 127) / 128);       // (32, 32)
    dim3 gFA(8, BB * HH);

    for (int l = 0; l < LL; l++) {
        const float* Wb = attn_b + (size_t)l * 4 * DD;
        const float* la = ln_a + (size_t)l * 2 * DD;
        const float* lb = ln_b + (size_t)l * 2 * DD;

        // attention sublayer (layer0 launches 3..6: #6 = tgemm<1> for ncu)
        ln_h_k<<<MM, 256>>>(h, la, lb, y);
        tgemm_k<0><<<gQKV, 256, GEMM_SMEM>>>(y,
            wq + (size_t)l*QKVN*DD, Wb, qkv, nullptr, MM, QKVN, DD);
        flash_k<<<gFA, 128>>>(qkv, o);
        tgemm_k<1><<<gD, 256, GEMM_SMEM>>>(o,
            wo + (size_t)l*DD*DD, Wb + 3*DD, h, nullptr, MM, DD, DD);

        // feed-forward sublayer
        ln_h_k<<<MM, 256>>>(h, la + DD, lb + DD, y);
        tgemm_k<2><<<gF, 256, GEMM_SMEM>>>(y,
            wf1 + (size_t)l*FF*DD, b1 + (size_t)l*FF, nullptr, f, MM, FF, DD);
        tgemm_k<1><<<gD, 256, GEMM_SMEM>>>(f,
            wf2 + (size_t)l*DD*FF, b2 + (size_t)l*DD, h, nullptr, MM, DD, FF);
    }

    layernorm_k<<<MM, 256>>>(h, na, nb, out);
}